// round 11
// baseline (speedup 1.0000x reference)
#include <cuda_runtime.h>
#include <cuda_bf16.h>
#include <math.h>

#define S_LEN 1024
#define CS 384
#define CZ 128
#define CH 256
#define NH 8
#define HD 32
#define PV 8
#define QKVP_N 832   // 256+256+256+64
#define INFV 100000.0f
#define SC_PITCH 1036

#define ZTILE_ROWS 32
#define ZTILE_FLOATS (ZTILE_ROWS * CZ)   // 4096 floats = 16KB
#define NSTAGES 3
#define NTILES (S_LEN / ZTILE_ROWS)      // 32
#define ZDYN_BYTES (NSTAGES * ZTILE_FLOATS * 4)  // 49152

// ---------------- scratch (__device__ globals, no allocation) ----------------
__device__ __align__(16) float g_sn[S_LEN * CS];
__device__ __align__(16) float g_qkvp[S_LEN * QKVP_N];
__device__ __align__(16) float g_scores[S_LEN * NH * S_LEN];   // layout [i][h][j]
__device__ __align__(16) float g_aop[4 * S_LEN * CH];          // split-K partials
__device__ __align__(16) float g_Wall[QKVP_N * CS];
__device__ __align__(16) float g_bias832[QKVP_N];
__device__ __align__(16) float g_gw[NH * CZ];
__device__ float g_gwsum[NH];
__device__ float g_bw[NH];
__device__ __align__(16) float g_maskbias[S_LEN];
__device__ __align__(16) float g_coords[S_LEN * 4];
__device__ __align__(16) float g_vp[S_LEN * 24];
__device__ __align__(16) float g_attpts[S_LEN * 24];

// ---------------- packed f32x2 helpers (sm_103a FFMA2) ----------------
__device__ __forceinline__ unsigned long long pk(float x, float y) {
    float2 v = make_float2(x, y);
    return *reinterpret_cast<unsigned long long*>(&v);
}
__device__ __forceinline__ float2 upk(unsigned long long u) {
    return *reinterpret_cast<float2*>(&u);
}
__device__ __forceinline__ unsigned long long fma2(unsigned long long a,
                                                   unsigned long long b,
                                                   unsigned long long c) {
    unsigned long long d;
    asm("fma.rn.f32x2 %0, %1, %2, %3;" : "=l"(d) : "l"(a), "l"(b), "l"(c));
    return d;
}
__device__ __forceinline__ unsigned long long add2(unsigned long long a,
                                                   unsigned long long b) {
    unsigned long long d;
    asm("add.rn.f32x2 %0, %1, %2;" : "=l"(d) : "l"(a), "l"(b));
    return d;
}

// ---------------- fused prep: ln_s + pack_w + prep_pair + coords + maskbias ----------------
__global__ void prep_fused(const float* __restrict__ s,
                           const float* __restrict__ ln_s_g, const float* __restrict__ ln_s_b,
                           const float* __restrict__ ln_z_g, const float* __restrict__ ln_z_b,
                           const float* __restrict__ W_pair,
                           const float* __restrict__ Wq, const float* __restrict__ Wk,
                           const float* __restrict__ Wv, const float* __restrict__ Wvp,
                           const float* __restrict__ bvp, const float* __restrict__ rigids,
                           const float* __restrict__ mask) {
    int b = blockIdx.x;
    int t = threadIdx.x;  // 128
    __shared__ float red[128];
    if (b < S_LEN) {
        const float* row = s + (long)b * CS;
        float x0 = row[t], x1 = row[t + 128], x2 = row[t + 256];
        red[t] = x0 + x1 + x2; __syncthreads();
        for (int st = 64; st > 0; st >>= 1) { if (t < st) red[t] += red[t + st]; __syncthreads(); }
        float mean = red[0] * (1.0f / CS);
        __syncthreads();
        float d0 = x0 - mean, d1 = x1 - mean, d2 = x2 - mean;
        red[t] = d0 * d0 + d1 * d1 + d2 * d2; __syncthreads();
        for (int st = 64; st > 0; st >>= 1) { if (t < st) red[t] += red[t + st]; __syncthreads(); }
        float r = rsqrtf(red[0] * (1.0f / CS) + 1e-5f);
        float* o = g_sn + (long)b * CS;
        o[t]       = d0 * r * ln_s_g[t]       + ln_s_b[t];
        o[t + 128] = d1 * r * ln_s_g[t + 128] + ln_s_b[t + 128];
        o[t + 256] = d2 * r * ln_s_g[t + 256] + ln_s_b[t + 256];
    } else if (b < S_LEN + 128) {
        int t2 = (b - S_LEN) * 128 + t;
        for (int idx = t2; idx < QKVP_N * CS; idx += 128 * 128) {
            int r = idx / CS, c = idx % CS;
            float v;
            if (r < 256)      v = Wq[r * CS + c];
            else if (r < 512) v = Wk[(r - 256) * CS + c];
            else if (r < 768) v = Wv[(r - 512) * CS + c];
            else              v = Wvp[(r - 768) * CS + c];
            g_Wall[idx] = v;
        }
        if (t2 < QKVP_N) g_bias832[t2] = (t2 >= 768) ? bvp[t2 - 768] : 0.0f;
    } else if (b == S_LEN + 128) {
        int c = t;  // 128
        for (int h = 0; h < NH; h++) {
            float w = W_pair[h * CZ + c];
            float gv = ln_z_g[c] * w;
            g_gw[h * CZ + c] = gv;
            red[c] = gv; __syncthreads();
            for (int st = 64; st > 0; st >>= 1) { if (c < st) red[c] += red[c + st]; __syncthreads(); }
            if (c == 0) g_gwsum[h] = red[0];
            __syncthreads();
            red[c] = ln_z_b[c] * w; __syncthreads();
            for (int st = 64; st > 0; st >>= 1) { if (c < st) red[c] += red[c + st]; __syncthreads(); }
            if (c == 0) g_bw[h] = red[0];
            __syncthreads();
        }
    } else if (b < S_LEN + 129 + 8) {
        int i = (b - (S_LEN + 129)) * 128 + t;
        if (i < S_LEN) {
            const float* rg = rigids + i * 16;
            float4 c;
            c.x = rg[3]; c.y = rg[7]; c.z = rg[11]; c.w = 0.0f;
            ((float4*)g_coords)[i] = c;
        }
    } else {
        int i = (b - (S_LEN + 137)) * 128 + t;
        if (i < S_LEN) {
            const float inv_scale = 5.656854249492381f;  // sqrt(32)
            g_maskbias[i] = INFV * (mask[i] - 1.0f) * inv_scale;
        }
    }
}

// ---------------- generic tiled GEMM ----------------
#define BM 64
#define BN 64
#define BK 16

__global__ void gemm_nt(const float* __restrict__ A, int lda, long sA,
                        const float* __restrict__ B, int ldb, long sB,
                        float* __restrict__ C, int ldc, long sC,
                        int M, int N, int K,
                        float alpha_const,
                        const float* __restrict__ bias) {
    A += (long)blockIdx.z * sA;
    B += (long)blockIdx.z * sB;
    C += (long)blockIdx.z * sC;
    int m0 = blockIdx.y * BM;
    int n0 = blockIdx.x * BN;
    __shared__ float As[BK][BM + 1];
    __shared__ float Bs[BK][BN + 1];
    int tid = threadIdx.x;
    int tx = tid % 16, ty = tid / 16;
    float acc[4][4] = {};
    for (int kt = 0; kt < K; kt += BK) {
#pragma unroll
        for (int p = 0; p < 4; p++) {
            int idx = p * 256 + tid;
            int ml = idx / BK, kl = idx % BK;
            float v = 0.0f;
            if (m0 + ml < M && kt + kl < K) v = A[(long)(m0 + ml) * lda + kt + kl];
            As[kl][ml] = v;
        }
#pragma unroll
        for (int p = 0; p < 4; p++) {
            int idx = p * 256 + tid;
            int nl = idx / BK, kl = idx % BK;
            float v = 0.0f;
            if (n0 + nl < N && kt + kl < K) v = B[(long)(n0 + nl) * ldb + kt + kl];
            Bs[kl][nl] = v;
        }
        __syncthreads();
#pragma unroll
        for (int k = 0; k < BK; k++) {
            float a[4], b[4];
#pragma unroll
            for (int i = 0; i < 4; i++) a[i] = As[k][ty * 4 + i];
#pragma unroll
            for (int j = 0; j < 4; j++) b[j] = Bs[k][tx * 4 + j];
#pragma unroll
            for (int i = 0; i < 4; i++)
#pragma unroll
                for (int j = 0; j < 4; j++) acc[i][j] = fmaf(a[i], b[j], acc[i][j]);
        }
        __syncthreads();
    }
#pragma unroll
    for (int i = 0; i < 4; i++) {
        int m = m0 + ty * 4 + i;
        if (m >= M) continue;
#pragma unroll
        for (int j = 0; j < 4; j++) {
            int n = n0 + tx * 4 + j;
            if (n >= N) continue;
            float v = acc[i][j];
            if (bias) v += bias[n];
            C[(long)m * ldc + n] = v * alpha_const;
        }
    }
}

// ---------------- split-K attn @ v (BK=32) ----------------
__global__ __launch_bounds__(256) void attnv_kernel() {
    int ks = blockIdx.x;
    int m0 = blockIdx.y * 64;
    int h  = blockIdx.z;
    const float* A = g_scores + (long)h * S_LEN;
    const float* B = g_qkvp + 512 + h * 32;
    float* C = g_aop + (long)ks * (S_LEN * CH);
    __shared__ float As[32][65];
    __shared__ float Bs[32][33];
    int tid = threadIdx.x;
    int tx = tid % 16, ty = tid / 16;
    float acc[4][2] = {};
    int k0 = ks * 256;
    for (int kt = 0; kt < 256; kt += 32) {
#pragma unroll
        for (int p = 0; p < 8; p++) {
            int idx = p * 256 + tid;
            int ml = idx / 32, kl = idx % 32;
            As[kl][ml] = A[(long)(m0 + ml) * (NH * S_LEN) + k0 + kt + kl];
        }
#pragma unroll
        for (int p = 0; p < 4; p++) {
            int idx = p * 256 + tid;
            int kl = idx / 32, nl = idx % 32;
            Bs[kl][nl] = B[(long)(k0 + kt + kl) * QKVP_N + nl];
        }
        __syncthreads();
#pragma unroll
        for (int k = 0; k < 32; k++) {
            float a[4], b[2];
#pragma unroll
            for (int i = 0; i < 4; i++) a[i] = As[k][ty * 4 + i];
#pragma unroll
            for (int j = 0; j < 2; j++) b[j] = Bs[k][tx * 2 + j];
#pragma unroll
            for (int i = 0; i < 4; i++)
#pragma unroll
                for (int j = 0; j < 2; j++) acc[i][j] = fmaf(a[i], b[j], acc[i][j]);
        }
        __syncthreads();
    }
#pragma unroll
    for (int i = 0; i < 4; i++)
#pragma unroll
        for (int j = 0; j < 2; j++)
            C[(long)(m0 + ty * 4 + i) * CH + h * 32 + tx * 2 + j] = acc[i][j];
}

// ---------------- fused z-pass v11: 3-stage cp.async, bf16 bias smem, 3 blocks/SM ----------------
__global__ __launch_bounds__(256, 3) void bias_softmax_kernel(const float* __restrict__ z) {
    extern __shared__ __align__(16) float zbuf[];        // NSTAGES * 16KB = 48KB
    __shared__ __nv_bfloat16 sc[NH * SC_PITCH];          // bias in bf16 (~16.6KB)

    int i = blockIdx.x;
    int tid = threadIdx.x;  // 256
    int w = tid >> 5, lane = tid & 31;
    int sub = lane >> 4, r16 = lane & 15;

    unsigned long long wa01[NH], wa23[NH], wc01[NH], wc23[NH];
#pragma unroll
    for (int h = 0; h < NH; h++) {
        float4 wa = *(const float4*)(g_gw + h * CZ + r16 * 4);
        float4 wc = *(const float4*)(g_gw + h * CZ + 64 + r16 * 4);
        wa01[h] = pk(wa.x, wa.y); wa23[h] = pk(wa.z, wa.w);
        wc01[h] = pk(wc.x, wc.y); wc23[h] = pk(wc.z, wc.w);
    }
    int h_own = (r16 >> 1) & 7;
    float gws_own = g_gwsum[h_own];
    float bw_own  = g_bw[h_own];
    bool wr_lane = ((r16 & 1) == 0);
    bool b3 = (r16 & 8) != 0, b2 = (r16 & 4) != 0, b1 = (r16 & 2) != 0;

    const float* zbase = z + ((long)i << 17);  // z[i]

#define ISSUE_TILE(T)                                                                   \
    do {                                                                                \
        if ((T) < NTILES) {                                                             \
            const float4* src = (const float4*)(zbase + (long)(T) * ZTILE_FLOATS);      \
            float4* dst = (float4*)(zbuf + ((T) % NSTAGES) * ZTILE_FLOATS);             \
            _Pragma("unroll")                                                           \
            for (int p = 0; p < 4; p++) {                                               \
                int c = tid + p * 256;                                                  \
                unsigned saddr = (unsigned)__cvta_generic_to_shared(dst + c);           \
                asm volatile("cp.async.cg.shared.global [%0], [%1], 16;"                \
                             :: "r"(saddr), "l"(src + c));                              \
            }                                                                           \
        }                                                                               \
        asm volatile("cp.async.commit_group;" ::);                                      \
    } while (0)

    ISSUE_TILE(0); ISSUE_TILE(1);

    for (int t = 0; t < NTILES; t++) {
        asm volatile("cp.async.wait_group %0;" :: "n"(1));
        __syncthreads();
        const float* sb = zbuf + (t % NSTAGES) * ZTILE_FLOATS;
#pragma unroll
        for (int it = 0; it < 2; it++) {
            int lrow = it * 16 + 2 * w + sub;   // 0..31
            const float4* zr = (const float4*)(sb + lrow * CZ);
            float4 A0 = zr[r16];
            float4 A1 = zr[16 + r16];
            unsigned long long za01 = pk(A0.x, A0.y), za23 = pk(A0.z, A0.w);
            unsigned long long zc01 = pk(A1.x, A1.y), zc23 = pk(A1.z, A1.w);
            unsigned long long sz2  = add2(add2(za01, za23), add2(zc01, zc23));
            unsigned long long szz2 = fma2(za01, za01, fma2(za23, za23,
                                      fma2(zc01, zc01, fma2(zc23, zc23, 0ull))));
            float dot[NH];
#pragma unroll
            for (int h = 0; h < NH; h++) {
                unsigned long long d2 = fma2(za01, wa01[h], fma2(za23, wa23[h],
                                        fma2(zc01, wc01[h], fma2(zc23, wc23[h], 0ull))));
                float2 d = upk(d2);
                dot[h] = d.x + d.y;
            }
            float2 s2 = upk(sz2);  float sz  = s2.x + s2.y;
            float2 q2 = upk(szz2); float szz = q2.x + q2.y;

#pragma unroll
            for (int o = 8; o >= 1; o >>= 1) {
                sz  += __shfl_xor_sync(0xffffffffu, sz, o);
                szz += __shfl_xor_sync(0xffffffffu, szz, o);
            }
#pragma unroll
            for (int k = 0; k < 8; k++) dot[k] += __shfl_xor_sync(0xffffffffu, dot[k], 8);
            float y0 = b3 ? dot[4] : dot[0];
            float y1 = b3 ? dot[5] : dot[1];
            float y2 = b3 ? dot[6] : dot[2];
            float y3 = b3 ? dot[7] : dot[3];
            y0 += __shfl_xor_sync(0xffffffffu, y0, 4);
            y1 += __shfl_xor_sync(0xffffffffu, y1, 4);
            y2 += __shfl_xor_sync(0xffffffffu, y2, 4);
            y3 += __shfl_xor_sync(0xffffffffu, y3, 4);
            float t0 = b2 ? y2 : y0;
            float t1 = b2 ? y3 : y1;
            t0 += __shfl_xor_sync(0xffffffffu, t0, 2);
            t1 += __shfl_xor_sync(0xffffffffu, t1, 2);
            float f = b1 ? t1 : t0;
            f += __shfl_xor_sync(0xffffffffu, f, 1);

            float mean = sz * (1.0f / CZ);
            float var = szz * (1.0f / CZ) - mean * mean;
            float r = rsqrtf(var + 1e-5f);
            if (wr_lane)
                sc[h_own * SC_PITCH + t * ZTILE_ROWS + lrow] =
                    __float2bfloat16(r * f - r * mean * gws_own + bw_own);
        }
        __syncthreads();
        ISSUE_TILE(t + 2);
    }
#undef ISSUE_TILE
    __syncthreads();

    // register-resident softmax: warp w owns head w (mask folded into qk scores)
    const float* qk = g_scores + (long)i * (NH * S_LEN) + (long)w * S_LEN;
    const __nv_bfloat16* bh = sc + w * SC_PITCH;
    float v[32];
    float m = -1e30f;
#pragma unroll
    for (int q = 0; q < 32; q++) {
        int jj = q * 32 + lane;
        float val = qk[jj] + __bfloat162float(bh[jj]);
        v[q] = val;
        m = fmaxf(m, val);
    }
#pragma unroll
    for (int o = 16; o > 0; o >>= 1) m = fmaxf(m, __shfl_xor_sync(0xffffffffu, m, o));
    float ssum = 0.0f;
#pragma unroll
    for (int q = 0; q < 32; q++) {
        float e = __expf(v[q] - m);
        v[q] = e;
        ssum += e;
    }
#pragma unroll
    for (int o = 16; o > 0; o >>= 1) ssum += __shfl_xor_sync(0xffffffffu, ssum, o);
    float rinv = 1.0f / ssum;
    float* outp = g_scores + (long)i * (NH * S_LEN) + (long)w * S_LEN;
#pragma unroll
    for (int q = 0; q < 32; q++) outp[q * 32 + lane] = v[q] * rinv;
}

// ---------------- point branch ----------------
__global__ void vp_kernel() {
    int i = blockIdx.x * blockDim.x + threadIdx.x;
    if (i >= S_LEN) return;
    float4 c = ((const float4*)g_coords)[i];
    const float* row = g_qkvp + (long)i * QKVP_N + 768;
#pragma unroll
    for (int h = 0; h < NH; h++) {
        float sm = 0.0f;
#pragma unroll
        for (int p = 0; p < PV; p++) sm += row[h * PV + p];
        g_vp[i * 24 + h * 3 + 0] = sm * c.x;
        g_vp[i * 24 + h * 3 + 1] = sm * c.y;
        g_vp[i * 24 + h * 3 + 2] = sm * c.z;
    }
}

__global__ __launch_bounds__(256) void point_kernel(const float* __restrict__ mask) {
    int i = blockIdx.x;
    int tid = threadIdx.x;  // 256
    __shared__ float svp[256 * 25];
    __shared__ float4 sco[256];
    __shared__ float sred[8 * 25];

    float4 ci = ((const float4*)g_coords)[i];
    float mi = mask[i];
    float acc[24] = {};
    float sw = 0.0f;

    for (int jt = 0; jt < 4; jt++) {
        int jbase = jt * 256;
        for (int idx = tid; idx < 256 * 24; idx += 256)
            svp[(idx / 24) * 25 + (idx % 24)] = g_vp[jbase * 24 + idx];
        sco[tid] = ((const float4*)g_coords)[jbase + tid];
        __syncthreads();
        int jl = tid;
        float4 cj = sco[jl];
        float dx = ci.x - cj.x, dy = ci.y - cj.y, dz = ci.z - cj.z;
        float dist = sqrtf(dx * dx + dy * dy + dz * dz + 1e-12f);
        float wgt = __expf(-dist * 0.1f) * mi * mask[jbase + jl];
        sw += wgt;
#pragma unroll
        for (int p = 0; p < 24; p++) acc[p] = fmaf(wgt, svp[jl * 25 + p], acc[p]);
        __syncthreads();
    }

    int wr = tid >> 5, lane = tid & 31;
#pragma unroll
    for (int o = 16; o > 0; o >>= 1) {
        sw += __shfl_xor_sync(0xffffffffu, sw, o);
#pragma unroll
        for (int p = 0; p < 24; p++) acc[p] += __shfl_xor_sync(0xffffffffu, acc[p], o);
    }
    if (lane == 0) {
#pragma unroll
        for (int p = 0; p < 24; p++) sred[wr * 25 + p] = acc[p];
        sred[wr * 25 + 24] = sw;
    }
    __syncthreads();
    if (tid < 24) {
        float s = 0.0f, swt = 0.0f;
#pragma unroll
        for (int k = 0; k < 8; k++) { s += sred[k * 25 + tid]; swt += sred[k * 25 + 24]; }
        g_attpts[i * 24 + tid] = s / (swt + 1e-8f);
    }
}

// ---------------- fused output epilogue ----------------
__global__ __launch_bounds__(256) void fused_out_kernel(const float* __restrict__ s,
                                                        const float* __restrict__ Wo,
                                                        const float* __restrict__ bo,
                                                        const float* __restrict__ W_po,
                                                        const float* __restrict__ b_po,
                                                        const float* __restrict__ w_scalar,
                                                        const float* __restrict__ w_point,
                                                        float* __restrict__ out) {
    int m0 = blockIdx.y * BM;
    int n0 = blockIdx.x * BN;
    __shared__ float As[BK][BM + 1];
    __shared__ float Bs[BK][BN + 1];
    int tid = threadIdx.x;
    int tx = tid % 16, ty = tid / 16;
    float acc1[4][4] = {};
    for (int kt = 0; kt < CH; kt += BK) {
#pragma unroll
        for (int p = 0; p < 4; p++) {
            int idx = p * 256 + tid;
            int ml = idx / BK, kl = idx % BK;
            long off = (long)(m0 + ml) * CH + kt + kl;
            As[kl][ml] = g_aop[off] + g_aop[S_LEN * CH + off] +
                         g_aop[2 * S_LEN * CH + off] + g_aop[3 * S_LEN * CH + off];
        }
#pragma unroll
        for (int p = 0; p < 4; p++) {
            int idx = p * 256 + tid;
            int nl = idx / BK, kl = idx % BK;
            Bs[kl][nl] = Wo[(long)(n0 + nl) * CH + kt + kl];
        }
        __syncthreads();
#pragma unroll
        for (int k = 0; k < BK; k++) {
            float a[4], b[4];
#pragma unroll
            for (int i = 0; i < 4; i++) a[i] = As[k][ty * 4 + i];
#pragma unroll
            for (int j = 0; j < 4; j++) b[j] = Bs[k][tx * 4 + j];
#pragma unroll
            for (int i = 0; i < 4; i++)
#pragma unroll
                for (int j = 0; j < 4; j++) acc1[i][j] = fmaf(a[i], b[j], acc1[i][j]);
        }
        __syncthreads();
    }
    __shared__ float As2[BM][25];
    __shared__ float Bs2[BN][25];
    for (int idx = tid; idx < BM * 24; idx += 256)
        As2[idx / 24][idx % 24] = g_attpts[(long)(m0 + idx / 24) * 24 + idx % 24];
    for (int idx = tid; idx < BN * 24; idx += 256)
        Bs2[idx / 24][idx % 24] = W_po[(long)(n0 + idx / 24) * 24 + idx % 24];
    __syncthreads();
    float acc2[4][4] = {};
#pragma unroll
    for (int k = 0; k < 24; k++) {
        float a[4], b[4];
#pragma unroll
        for (int i = 0; i < 4; i++) a[i] = As2[ty * 4 + i][k];
#pragma unroll
        for (int j = 0; j < 4; j++) b[j] = Bs2[tx * 4 + j][k];
#pragma unroll
        for (int i = 0; i < 4; i++)
#pragma unroll
            for (int j = 0; j < 4; j++) acc2[i][j] = fmaf(a[i], b[j], acc2[i][j]);
    }
    float ws = *w_scalar, wp = *w_point;
#pragma unroll
    for (int i = 0; i < 4; i++) {
        int m = m0 + ty * 4 + i;
#pragma unroll
        for (int j = 0; j < 4; j++) {
            int n = n0 + tx * 4 + j;
            out[(long)m * CS + n] = s[(long)m * CS + n]
                + ws * (acc1[i][j] + bo[n])
                + wp * (acc2[i][j] + b_po[n]);
        }
    }
}

// ---------------- launch ----------------
extern "C" void kernel_launch(void* const* d_in, const int* in_sizes, int n_in,
                              void* d_out, int out_size) {
    const float* s       = (const float*)d_in[0];
    const float* z       = (const float*)d_in[1];
    const float* rigids  = (const float*)d_in[2];
    const float* mask    = (const float*)d_in[3];
    const float* ln_s_g  = (const float*)d_in[4];
    const float* ln_s_b  = (const float*)d_in[5];
    const float* ln_z_g  = (const float*)d_in[6];
    const float* ln_z_b  = (const float*)d_in[7];
    const float* Wq      = (const float*)d_in[8];
    const float* Wk      = (const float*)d_in[9];
    const float* Wv      = (const float*)d_in[10];
    const float* W_pair  = (const float*)d_in[11];
    const float* Wo      = (const float*)d_in[12];
    const float* bo      = (const float*)d_in[13];
    const float* Wvp     = (const float*)d_in[14];
    const float* bvp     = (const float*)d_in[15];
    const float* W_po    = (const float*)d_in[16];
    const float* b_po    = (const float*)d_in[17];
    const float* w_scalar= (const float*)d_in[18];
    const float* w_point = (const float*)d_in[19];
    float* out = (float*)d_out;

    float *p_sn, *p_qkvp, *p_scores, *p_Wall, *p_bias832, *p_maskbias;
    cudaGetSymbolAddress((void**)&p_sn,       g_sn);
    cudaGetSymbolAddress((void**)&p_qkvp,     g_qkvp);
    cudaGetSymbolAddress((void**)&p_scores,   g_scores);
    cudaGetSymbolAddress((void**)&p_Wall,     g_Wall);
    cudaGetSymbolAddress((void**)&p_bias832,  g_bias832);
    cudaGetSymbolAddress((void**)&p_maskbias, g_maskbias);

    static int smem_set = 0;
    if (!smem_set) {
        cudaFuncSetAttribute(bias_softmax_kernel,
                             cudaFuncAttributeMaxDynamicSharedMemorySize, ZDYN_BYTES);
        smem_set = 1;
    }

    const float scale = 0.17677669529663687f;  // 1/sqrt(32)

    // 1: fused prep
    prep_fused<<<S_LEN + 129 + 8 + 8, 128>>>(s, ln_s_g, ln_s_b, ln_z_g, ln_z_b, W_pair,
                                             Wq, Wk, Wv, Wvp, bvp, rigids, mask);

    // 2: qkvp = s_n @ Wall^T + bias832
    {
        dim3 grid((QKVP_N + BN - 1) / BN, (S_LEN + BM - 1) / BM, 1);
        gemm_nt<<<grid, 256>>>(p_sn, CS, 0, p_Wall, CS, 0, p_qkvp, QKVP_N, 0,
                               S_LEN, QKVP_N, CS, 1.0f, p_bias832);
    }
    // 3: qk scores per head (layout [i][h][j]); mask folded via bias
    {
        dim3 grid(S_LEN / BN, S_LEN / BM, NH);
        gemm_nt<<<grid, 256>>>(p_qkvp, QKVP_N, 32,
                               p_qkvp + 256, QKVP_N, 32,
                               p_scores, NH * S_LEN, S_LEN,
                               S_LEN, S_LEN, HD, scale, p_maskbias);
    }

    // 4: the big fused z pass (profiled slot)
    bias_softmax_kernel<<<S_LEN, 256, ZDYN_BYTES>>>(z);

    vp_kernel<<<4, 256>>>();
    point_kernel<<<S_LEN, 256>>>(mask);

    // split-K attn @ v
    {
        dim3 grid(4, S_LEN / 64, NH);
        attnv_kernel<<<grid, 256>>>();
    }

    // fused output epilogue
    {
        dim3 grid(CS / BN, S_LEN / BM, 1);
        fused_out_kernel<<<grid, 256>>>(s, Wo, bo, W_po, b_po, w_scalar, w_point, out);
    }
}

// round 12
// speedup vs baseline: 1.1637x; 1.1637x over previous
#include <cuda_runtime.h>
#include <cuda_bf16.h>
#include <math.h>

#define S_LEN 1024
#define CS 384
#define CZ 128
#define CH 256
#define NH 8
#define HD 32
#define PV 8
#define QKVP_N 832   // 256+256+256+64
#define INFV 100000.0f
#define SC_PITCH 1036

#define ZTILE_ROWS 32
#define ZTILE_FLOATS (ZTILE_ROWS * CZ)   // 4096 floats = 16KB
#define NSTAGES 4
#define NTILES (S_LEN / ZTILE_ROWS)      // 32
#define ZDYN_BYTES (NSTAGES * ZTILE_FLOATS * 4)  // 65536

// ---------------- scratch (__device__ globals, no allocation) ----------------
__device__ __align__(16) __nv_bfloat16 g_sn_bf[S_LEN * CS];
__device__ __align__(16) __nv_bfloat16 g_Wall_bf[QKVP_N * CS];
__device__ __align__(16) float g_qkvp[S_LEN * QKVP_N];
__device__ __align__(16) float g_scores[S_LEN * NH * S_LEN];   // layout [i][h][j]
__device__ __align__(16) float g_aop[4 * S_LEN * CH];          // split-K partials
__device__ __align__(16) float g_bias832[QKVP_N];
__device__ __align__(16) float g_gw[NH * CZ];
__device__ float g_gwsum[NH];
__device__ float g_bw[NH];
__device__ __align__(16) float g_maskbias[S_LEN];
__device__ __align__(16) float g_coords[S_LEN * 4];
__device__ __align__(16) float g_vp[S_LEN * 24];
__device__ __align__(16) float g_attpts[S_LEN * 24];

// ---------------- packed f32x2 helpers (sm_103a FFMA2) ----------------
__device__ __forceinline__ unsigned long long pk(float x, float y) {
    float2 v = make_float2(x, y);
    return *reinterpret_cast<unsigned long long*>(&v);
}
__device__ __forceinline__ float2 upk(unsigned long long u) {
    return *reinterpret_cast<float2*>(&u);
}
__device__ __forceinline__ unsigned long long fma2(unsigned long long a,
                                                   unsigned long long b,
                                                   unsigned long long c) {
    unsigned long long d;
    asm("fma.rn.f32x2 %0, %1, %2, %3;" : "=l"(d) : "l"(a), "l"(b), "l"(c));
    return d;
}
__device__ __forceinline__ unsigned long long add2(unsigned long long a,
                                                   unsigned long long b) {
    unsigned long long d;
    asm("add.rn.f32x2 %0, %1, %2;" : "=l"(d) : "l"(a), "l"(b));
    return d;
}

// ---------------- fused prep: ln_s(bf16) + pack_w(bf16) + prep_pair + coords + maskbias ----------------
__global__ void prep_fused(const float* __restrict__ s,
                           const float* __restrict__ ln_s_g, const float* __restrict__ ln_s_b,
                           const float* __restrict__ ln_z_g, const float* __restrict__ ln_z_b,
                           const float* __restrict__ W_pair,
                           const float* __restrict__ Wq, const float* __restrict__ Wk,
                           const float* __restrict__ Wv, const float* __restrict__ Wvp,
                           const float* __restrict__ bvp, const float* __restrict__ rigids,
                           const float* __restrict__ mask) {
    int b = blockIdx.x;
    int t = threadIdx.x;  // 128
    __shared__ float red[128];
    if (b < S_LEN) {
        const float* row = s + (long)b * CS;
        float x0 = row[t], x1 = row[t + 128], x2 = row[t + 256];
        red[t] = x0 + x1 + x2; __syncthreads();
        for (int st = 64; st > 0; st >>= 1) { if (t < st) red[t] += red[t + st]; __syncthreads(); }
        float mean = red[0] * (1.0f / CS);
        __syncthreads();
        float d0 = x0 - mean, d1 = x1 - mean, d2 = x2 - mean;
        red[t] = d0 * d0 + d1 * d1 + d2 * d2; __syncthreads();
        for (int st = 64; st > 0; st >>= 1) { if (t < st) red[t] += red[t + st]; __syncthreads(); }
        float r = rsqrtf(red[0] * (1.0f / CS) + 1e-5f);
        __nv_bfloat16* o = g_sn_bf + (long)b * CS;
        o[t]       = __float2bfloat16(d0 * r * ln_s_g[t]       + ln_s_b[t]);
        o[t + 128] = __float2bfloat16(d1 * r * ln_s_g[t + 128] + ln_s_b[t + 128]);
        o[t + 256] = __float2bfloat16(d2 * r * ln_s_g[t + 256] + ln_s_b[t + 256]);
    } else if (b < S_LEN + 128) {
        int t2 = (b - S_LEN) * 128 + t;
        for (int idx = t2; idx < QKVP_N * CS; idx += 128 * 128) {
            int r = idx / CS, c = idx % CS;
            float v;
            if (r < 256)      v = Wq[r * CS + c];
            else if (r < 512) v = Wk[(r - 256) * CS + c];
            else if (r < 768) v = Wv[(r - 512) * CS + c];
            else              v = Wvp[(r - 768) * CS + c];
            g_Wall_bf[idx] = __float2bfloat16(v);
        }
        if (t2 < QKVP_N) g_bias832[t2] = (t2 >= 768) ? bvp[t2 - 768] : 0.0f;
    } else if (b == S_LEN + 128) {
        int c = t;  // 128
        for (int h = 0; h < NH; h++) {
            float w = W_pair[h * CZ + c];
            float gv = ln_z_g[c] * w;
            g_gw[h * CZ + c] = gv;
            red[c] = gv; __syncthreads();
            for (int st = 64; st > 0; st >>= 1) { if (c < st) red[c] += red[c + st]; __syncthreads(); }
            if (c == 0) g_gwsum[h] = red[0];
            __syncthreads();
            red[c] = ln_z_b[c] * w; __syncthreads();
            for (int st = 64; st > 0; st >>= 1) { if (c < st) red[c] += red[c + st]; __syncthreads(); }
            if (c == 0) g_bw[h] = red[0];
            __syncthreads();
        }
    } else if (b < S_LEN + 129 + 8) {
        int i = (b - (S_LEN + 129)) * 128 + t;
        if (i < S_LEN) {
            const float* rg = rigids + i * 16;
            float4 c;
            c.x = rg[3]; c.y = rg[7]; c.z = rg[11]; c.w = 0.0f;
            ((float4*)g_coords)[i] = c;
        }
    } else {
        int i = (b - (S_LEN + 137)) * 128 + t;
        if (i < S_LEN) {
            const float inv_scale = 5.656854249492381f;  // sqrt(32)
            g_maskbias[i] = INFV * (mask[i] - 1.0f) * inv_scale;
        }
    }
}

// ---------------- qkvp via bf16 tensor-core mma (m16n8k16) ----------------
// Block tile 64x64, 8 warps of 16x32. A = sn_bf [M][K], B = Wall_bf [N][K] (col-major B).
#define AS_STRIDE 24   // padded bf16 row stride (48B = 12 banks): conflict-free frag loads
__global__ __launch_bounds__(256) void qkvp_mma_kernel() {
    __shared__ __nv_bfloat16 As[64][AS_STRIDE];
    __shared__ __nv_bfloat16 Bs[64][AS_STRIDE];
    int tid = threadIdx.x;
    int warp = tid >> 5, lane = tid & 31;
    int m0 = blockIdx.y * 64, n0 = blockIdx.x * 64;
    int wm = (warp & 3) * 16, wn = (warp >> 2) * 32;
    int g = lane >> 2, t = lane & 3;

    float c[4][4] = {};
    for (int kt = 0; kt < CS; kt += 16) {
        // stage tiles (each thread: 2 b32 for A, 2 for B)
#pragma unroll
        for (int p = 0; p < 2; p++) {
            int idx = tid + p * 256;
            int row = idx >> 3, cc = (idx & 7) * 2;
            *(unsigned*)&As[row][cc] =
                *(const unsigned*)&g_sn_bf[(long)(m0 + row) * CS + kt + cc];
            *(unsigned*)&Bs[row][cc] =
                *(const unsigned*)&g_Wall_bf[(long)(n0 + row) * CS + kt + cc];
        }
        __syncthreads();
        // A fragment for this warp's 16-row slice
        unsigned a0 = *(const unsigned*)&As[wm + g][t * 2];
        unsigned a1 = *(const unsigned*)&As[wm + g + 8][t * 2];
        unsigned a2 = *(const unsigned*)&As[wm + g][t * 2 + 8];
        unsigned a3 = *(const unsigned*)&As[wm + g + 8][t * 2 + 8];
#pragma unroll
        for (int f = 0; f < 4; f++) {
            unsigned b0 = *(const unsigned*)&Bs[wn + f * 8 + g][t * 2];
            unsigned b1 = *(const unsigned*)&Bs[wn + f * 8 + g][t * 2 + 8];
            asm volatile(
                "mma.sync.aligned.m16n8k16.row.col.f32.bf16.bf16.f32 "
                "{%0,%1,%2,%3}, {%4,%5,%6,%7}, {%8,%9}, {%0,%1,%2,%3};"
                : "+f"(c[f][0]), "+f"(c[f][1]), "+f"(c[f][2]), "+f"(c[f][3])
                : "r"(a0), "r"(a1), "r"(a2), "r"(a3), "r"(b0), "r"(b1));
        }
        __syncthreads();
    }
    // epilogue: add bias, store fp32
#pragma unroll
    for (int f = 0; f < 4; f++) {
        int col = n0 + wn + f * 8 + t * 2;
        float b0 = g_bias832[col], b1 = g_bias832[col + 1];
        int row0 = m0 + wm + g, row1 = row0 + 8;
        *(float2*)&g_qkvp[(long)row0 * QKVP_N + col] = make_float2(c[f][0] + b0, c[f][1] + b1);
        *(float2*)&g_qkvp[(long)row1 * QKVP_N + col] = make_float2(c[f][2] + b0, c[f][3] + b1);
    }
}

// ---------------- generic tiled GEMM (qk scores) ----------------
#define BM 64
#define BN 64
#define BK 16

__global__ void gemm_nt(const float* __restrict__ A, int lda, long sA,
                        const float* __restrict__ B, int ldb, long sB,
                        float* __restrict__ C, int ldc, long sC,
                        int M, int N, int K,
                        float alpha_const,
                        const float* __restrict__ bias) {
    A += (long)blockIdx.z * sA;
    B += (long)blockIdx.z * sB;
    C += (long)blockIdx.z * sC;
    int m0 = blockIdx.y * BM;
    int n0 = blockIdx.x * BN;
    __shared__ float As[BK][BM + 1];
    __shared__ float Bs[BK][BN + 1];
    int tid = threadIdx.x;
    int tx = tid % 16, ty = tid / 16;
    float acc[4][4] = {};
    for (int kt = 0; kt < K; kt += BK) {
#pragma unroll
        for (int p = 0; p < 4; p++) {
            int idx = p * 256 + tid;
            int ml = idx / BK, kl = idx % BK;
            float v = 0.0f;
            if (m0 + ml < M && kt + kl < K) v = A[(long)(m0 + ml) * lda + kt + kl];
            As[kl][ml] = v;
        }
#pragma unroll
        for (int p = 0; p < 4; p++) {
            int idx = p * 256 + tid;
            int nl = idx / BK, kl = idx % BK;
            float v = 0.0f;
            if (n0 + nl < N && kt + kl < K) v = B[(long)(n0 + nl) * ldb + kt + kl];
            Bs[kl][nl] = v;
        }
        __syncthreads();
#pragma unroll
        for (int k = 0; k < BK; k++) {
            float a[4], b[4];
#pragma unroll
            for (int i = 0; i < 4; i++) a[i] = As[k][ty * 4 + i];
#pragma unroll
            for (int j = 0; j < 4; j++) b[j] = Bs[k][tx * 4 + j];
#pragma unroll
            for (int i = 0; i < 4; i++)
#pragma unroll
                for (int j = 0; j < 4; j++) acc[i][j] = fmaf(a[i], b[j], acc[i][j]);
        }
        __syncthreads();
    }
#pragma unroll
    for (int i = 0; i < 4; i++) {
        int m = m0 + ty * 4 + i;
        if (m >= M) continue;
#pragma unroll
        for (int j = 0; j < 4; j++) {
            int n = n0 + tx * 4 + j;
            if (n >= N) continue;
            float v = acc[i][j];
            if (bias) v += bias[n];
            C[(long)m * ldc + n] = v * alpha_const;
        }
    }
}

// ---------------- split-K attn @ v (BK=32) ----------------
__global__ __launch_bounds__(256) void attnv_kernel() {
    int ks = blockIdx.x;
    int m0 = blockIdx.y * 64;
    int h  = blockIdx.z;
    const float* A = g_scores + (long)h * S_LEN;
    const float* B = g_qkvp + 512 + h * 32;
    float* C = g_aop + (long)ks * (S_LEN * CH);
    __shared__ float As[32][65];
    __shared__ float Bs[32][33];
    int tid = threadIdx.x;
    int tx = tid % 16, ty = tid / 16;
    float acc[4][2] = {};
    int k0 = ks * 256;
    for (int kt = 0; kt < 256; kt += 32) {
#pragma unroll
        for (int p = 0; p < 8; p++) {
            int idx = p * 256 + tid;
            int ml = idx / 32, kl = idx % 32;
            As[kl][ml] = A[(long)(m0 + ml) * (NH * S_LEN) + k0 + kt + kl];
        }
#pragma unroll
        for (int p = 0; p < 4; p++) {
            int idx = p * 256 + tid;
            int kl = idx / 32, nl = idx % 32;
            Bs[kl][nl] = B[(long)(k0 + kt + kl) * QKVP_N + nl];
        }
        __syncthreads();
#pragma unroll
        for (int k = 0; k < 32; k++) {
            float a[4], b[2];
#pragma unroll
            for (int i = 0; i < 4; i++) a[i] = As[k][ty * 4 + i];
#pragma unroll
            for (int j = 0; j < 2; j++) b[j] = Bs[k][tx * 2 + j];
#pragma unroll
            for (int i = 0; i < 4; i++)
#pragma unroll
                for (int j = 0; j < 2; j++) acc[i][j] = fmaf(a[i], b[j], acc[i][j]);
        }
        __syncthreads();
    }
#pragma unroll
    for (int i = 0; i < 4; i++)
#pragma unroll
        for (int j = 0; j < 2; j++)
            C[(long)(m0 + ty * 4 + i) * CH + h * 32 + tx * 2 + j] = acc[i][j];
}

// ---------------- fused z-pass (R5/R9 config, frozen): 4x16KB cp.async + smem sc ----------------
__global__ __launch_bounds__(256) void bias_softmax_kernel(const float* __restrict__ z) {
    extern __shared__ __align__(16) float zbuf[];  // NSTAGES * ZTILE_FLOATS (64KB)
    __shared__ float sc[NH * SC_PITCH];            // bias; then scores for softmax

    int i = blockIdx.x;
    int tid = threadIdx.x;  // 256
    int w = tid >> 5, lane = tid & 31;
    int sub = lane >> 4, r16 = lane & 15;

    unsigned long long wa01[NH], wa23[NH], wc01[NH], wc23[NH];
#pragma unroll
    for (int h = 0; h < NH; h++) {
        float4 wa = *(const float4*)(g_gw + h * CZ + r16 * 4);
        float4 wc = *(const float4*)(g_gw + h * CZ + 64 + r16 * 4);
        wa01[h] = pk(wa.x, wa.y); wa23[h] = pk(wa.z, wa.w);
        wc01[h] = pk(wc.x, wc.y); wc23[h] = pk(wc.z, wc.w);
    }
    int h_own = (r16 >> 1) & 7;
    float gws_own = g_gwsum[h_own];
    float bw_own  = g_bw[h_own];
    bool wr_lane = ((r16 & 1) == 0);
    bool b3 = (r16 & 8) != 0, b2 = (r16 & 4) != 0, b1 = (r16 & 2) != 0;

    const float* zbase = z + ((long)i << 17);  // z[i]

#define ISSUE_TILE(T)                                                                   \
    do {                                                                                \
        if ((T) < NTILES) {                                                             \
            const float4* src = (const float4*)(zbase + (long)(T) * ZTILE_FLOATS);      \
            float4* dst = (float4*)(zbuf + ((T) % NSTAGES) * ZTILE_FLOATS);             \
            _Pragma("unroll")                                                           \
            for (int p = 0; p < 4; p++) {                                               \
                int c = tid + p * 256;                                                  \
                unsigned saddr = (unsigned)__cvta_generic_to_shared(dst + c);           \
                asm volatile("cp.async.cg.shared.global [%0], [%1], 16;"                \
                             :: "r"(saddr), "l"(src + c));                              \
            }                                                                           \
        }                                                                               \
        asm volatile("cp.async.commit_group;" ::);                                      \
    } while (0)

    ISSUE_TILE(0); ISSUE_TILE(1); ISSUE_TILE(2);

    for (int t = 0; t < NTILES; t++) {
        asm volatile("cp.async.wait_group %0;" :: "n"(2));
        __syncthreads();
        const float* sb = zbuf + (t % NSTAGES) * ZTILE_FLOATS;
#pragma unroll
        for (int it = 0; it < 2; it++) {
            int lrow = it * 16 + 2 * w + sub;   // 0..31
            const float4* zr = (const float4*)(sb + lrow * CZ);
            float4 A0 = zr[r16];
            float4 A1 = zr[16 + r16];
            unsigned long long za01 = pk(A0.x, A0.y), za23 = pk(A0.z, A0.w);
            unsigned long long zc01 = pk(A1.x, A1.y), zc23 = pk(A1.z, A1.w);
            unsigned long long sz2  = add2(add2(za01, za23), add2(zc01, zc23));
            unsigned long long szz2 = fma2(za01, za01, fma2(za23, za23,
                                      fma2(zc01, zc01, fma2(zc23, zc23, 0ull))));
            float dot[NH];
#pragma unroll
            for (int h = 0; h < NH; h++) {
                unsigned long long d2 = fma2(za01, wa01[h], fma2(za23, wa23[h],
                                        fma2(zc01, wc01[h], fma2(zc23, wc23[h], 0ull))));
                float2 d = upk(d2);
                dot[h] = d.x + d.y;
            }
            float2 s2 = upk(sz2);  float sz  = s2.x + s2.y;
            float2 q2 = upk(szz2); float szz = q2.x + q2.y;

#pragma unroll
            for (int o = 8; o >= 1; o >>= 1) {
                sz  += __shfl_xor_sync(0xffffffffu, sz, o);
                szz += __shfl_xor_sync(0xffffffffu, szz, o);
            }
#pragma unroll
            for (int k = 0; k < 8; k++) dot[k] += __shfl_xor_sync(0xffffffffu, dot[k], 8);
            float y0 = b3 ? dot[4] : dot[0];
            float y1 = b3 ? dot[5] : dot[1];
            float y2 = b3 ? dot[6] : dot[2];
            float y3 = b3 ? dot[7] : dot[3];
            y0 += __shfl_xor_sync(0xffffffffu, y0, 4);
            y1 += __shfl_xor_sync(0xffffffffu, y1, 4);
            y2 += __shfl_xor_sync(0xffffffffu, y2, 4);
            y3 += __shfl_xor_sync(0xffffffffu, y3, 4);
            float t0 = b2 ? y2 : y0;
            float t1 = b2 ? y3 : y1;
            t0 += __shfl_xor_sync(0xffffffffu, t0, 2);
            t1 += __shfl_xor_sync(0xffffffffu, t1, 2);
            float f = b1 ? t1 : t0;
            f += __shfl_xor_sync(0xffffffffu, f, 1);

            float mean = sz * (1.0f / CZ);
            float var = szz * (1.0f / CZ) - mean * mean;
            float r = rsqrtf(var + 1e-5f);
            if (wr_lane)
                sc[h_own * SC_PITCH + t * ZTILE_ROWS + lrow] =
                    r * f - r * mean * gws_own + bw_own;
        }
        __syncthreads();
        ISSUE_TILE(t + 3);
    }
#undef ISSUE_TILE
    __syncthreads();

    // softmax: warp w owns head w (mask already folded into qk scores)
    float* srw = sc + w * SC_PITCH;
    const float* qk = g_scores + (long)i * (NH * S_LEN) + (long)w * S_LEN;
    float m = -1e30f;
    for (int jj = lane; jj < S_LEN; jj += 32) {
        float val = qk[jj] + srw[jj];
        srw[jj] = val;
        m = fmaxf(m, val);
    }
#pragma unroll
    for (int o = 16; o > 0; o >>= 1) m = fmaxf(m, __shfl_xor_sync(0xffffffffu, m, o));
    float ssum = 0.0f;
    for (int jj = lane; jj < S_LEN; jj += 32) {
        float e = __expf(srw[jj] - m);
        srw[jj] = e;
        ssum += e;
    }
#pragma unroll
    for (int o = 16; o > 0; o >>= 1) ssum += __shfl_xor_sync(0xffffffffu, ssum, o);
    float rinv = 1.0f / ssum;
    float* outp = g_scores + (long)i * (NH * S_LEN) + (long)w * S_LEN;
    for (int jj = lane; jj < S_LEN; jj += 32) outp[jj] = srw[jj] * rinv;
}

// ---------------- point branch ----------------
__global__ void vp_kernel() {
    int i = blockIdx.x * blockDim.x + threadIdx.x;
    if (i >= S_LEN) return;
    float4 c = ((const float4*)g_coords)[i];
    const float* row = g_qkvp + (long)i * QKVP_N + 768;
#pragma unroll
    for (int h = 0; h < NH; h++) {
        float sm = 0.0f;
#pragma unroll
        for (int p = 0; p < PV; p++) sm += row[h * PV + p];
        g_vp[i * 24 + h * 3 + 0] = sm * c.x;
        g_vp[i * 24 + h * 3 + 1] = sm * c.y;
        g_vp[i * 24 + h * 3 + 2] = sm * c.z;
    }
}

__global__ __launch_bounds__(256) void point_kernel(const float* __restrict__ mask) {
    int i = blockIdx.x;
    int tid = threadIdx.x;  // 256
    __shared__ float svp[256 * 25];
    __shared__ float4 sco[256];
    __shared__ float sred[8 * 25];

    float4 ci = ((const float4*)g_coords)[i];
    float mi = mask[i];
    float acc[24] = {};
    float sw = 0.0f;

    for (int jt = 0; jt < 4; jt++) {
        int jbase = jt * 256;
        for (int idx = tid; idx < 256 * 24; idx += 256)
            svp[(idx / 24) * 25 + (idx % 24)] = g_vp[jbase * 24 + idx];
        sco[tid] = ((const float4*)g_coords)[jbase + tid];
        __syncthreads();
        int jl = tid;
        float4 cj = sco[jl];
        float dx = ci.x - cj.x, dy = ci.y - cj.y, dz = ci.z - cj.z;
        float dist = sqrtf(dx * dx + dy * dy + dz * dz + 1e-12f);
        float wgt = __expf(-dist * 0.1f) * mi * mask[jbase + jl];
        sw += wgt;
#pragma unroll
        for (int p = 0; p < 24; p++) acc[p] = fmaf(wgt, svp[jl * 25 + p], acc[p]);
        __syncthreads();
    }

    int wr = tid >> 5, lane = tid & 31;
#pragma unroll
    for (int o = 16; o > 0; o >>= 1) {
        sw += __shfl_xor_sync(0xffffffffu, sw, o);
#pragma unroll
        for (int p = 0; p < 24; p++) acc[p] += __shfl_xor_sync(0xffffffffu, acc[p], o);
    }
    if (lane == 0) {
#pragma unroll
        for (int p = 0; p < 24; p++) sred[wr * 25 + p] = acc[p];
        sred[wr * 25 + 24] = sw;
    }
    __syncthreads();
    if (tid < 24) {
        float s = 0.0f, swt = 0.0f;
#pragma unroll
        for (int k = 0; k < 8; k++) { s += sred[k * 25 + tid]; swt += sred[k * 25 + 24]; }
        g_attpts[i * 24 + tid] = s / (swt + 1e-8f);
    }
}

// ---------------- fused output epilogue ----------------
__global__ __launch_bounds__(256) void fused_out_kernel(const float* __restrict__ s,
                                                        const float* __restrict__ Wo,
                                                        const float* __restrict__ bo,
                                                        const float* __restrict__ W_po,
                                                        const float* __restrict__ b_po,
                                                        const float* __restrict__ w_scalar,
                                                        const float* __restrict__ w_point,
                                                        float* __restrict__ out) {
    int m0 = blockIdx.y * BM;
    int n0 = blockIdx.x * BN;
    __shared__ float As[BK][BM + 1];
    __shared__ float Bs[BK][BN + 1];
    int tid = threadIdx.x;
    int tx = tid % 16, ty = tid / 16;
    float acc1[4][4] = {};
    for (int kt = 0; kt < CH; kt += BK) {
#pragma unroll
        for (int p = 0; p < 4; p++) {
            int idx = p * 256 + tid;
            int ml = idx / BK, kl = idx % BK;
            long off = (long)(m0 + ml) * CH + kt + kl;
            As[kl][ml] = g_aop[off] + g_aop[S_LEN * CH + off] +
                         g_aop[2 * S_LEN * CH + off] + g_aop[3 * S_LEN * CH + off];
        }
#pragma unroll
        for (int p = 0; p < 4; p++) {
            int idx = p * 256 + tid;
            int nl = idx / BK, kl = idx % BK;
            Bs[kl][nl] = Wo[(long)(n0 + nl) * CH + kt + kl];
        }
        __syncthreads();
#pragma unroll
        for (int k = 0; k < BK; k++) {
            float a[4], b[4];
#pragma unroll
            for (int i = 0; i < 4; i++) a[i] = As[k][ty * 4 + i];
#pragma unroll
            for (int j = 0; j < 4; j++) b[j] = Bs[k][tx * 4 + j];
#pragma unroll
            for (int i = 0; i < 4; i++)
#pragma unroll
                for (int j = 0; j < 4; j++) acc1[i][j] = fmaf(a[i], b[j], acc1[i][j]);
        }
        __syncthreads();
    }
    __shared__ float As2[BM][25];
    __shared__ float Bs2[BN][25];
    for (int idx = tid; idx < BM * 24; idx += 256)
        As2[idx / 24][idx % 24] = g_attpts[(long)(m0 + idx / 24) * 24 + idx % 24];
    for (int idx = tid; idx < BN * 24; idx += 256)
        Bs2[idx / 24][idx % 24] = W_po[(long)(n0 + idx / 24) * 24 + idx % 24];
    __syncthreads();
    float acc2[4][4] = {};
#pragma unroll
    for (int k = 0; k < 24; k++) {
        float a[4], b[4];
#pragma unroll
        for (int i = 0; i < 4; i++) a[i] = As2[ty * 4 + i][k];
#pragma unroll
        for (int j = 0; j < 4; j++) b[j] = Bs2[tx * 4 + j][k];
#pragma unroll
        for (int i = 0; i < 4; i++)
#pragma unroll
            for (int j = 0; j < 4; j++) acc2[i][j] = fmaf(a[i], b[j], acc2[i][j]);
    }
    float ws = *w_scalar, wp = *w_point;
#pragma unroll
    for (int i = 0; i < 4; i++) {
        int m = m0 + ty * 4 + i;
#pragma unroll
        for (int j = 0; j < 4; j++) {
            int n = n0 + tx * 4 + j;
            out[(long)m * CS + n] = s[(long)m * CS + n]
                + ws * (acc1[i][j] + bo[n])
                + wp * (acc2[i][j] + b_po[n]);
        }
    }
}

// ---------------- launch ----------------
extern "C" void kernel_launch(void* const* d_in, const int* in_sizes, int n_in,
                              void* d_out, int out_size) {
    const float* s       = (const float*)d_in[0];
    const float* z       = (const float*)d_in[1];
    const float* rigids  = (const float*)d_in[2];
    const float* mask    = (const float*)d_in[3];
    const float* ln_s_g  = (const float*)d_in[4];
    const float* ln_s_b  = (const float*)d_in[5];
    const float* ln_z_g  = (const float*)d_in[6];
    const float* ln_z_b  = (const float*)d_in[7];
    const float* Wq      = (const float*)d_in[8];
    const float* Wk      = (const float*)d_in[9];
    const float* Wv      = (const float*)d_in[10];
    const float* W_pair  = (const float*)d_in[11];
    const float* Wo      = (const float*)d_in[12];
    const float* bo      = (const float*)d_in[13];
    const float* Wvp     = (const float*)d_in[14];
    const float* bvp     = (const float*)d_in[15];
    const float* W_po    = (const float*)d_in[16];
    const float* b_po    = (const float*)d_in[17];
    const float* w_scalar= (const float*)d_in[18];
    const float* w_point = (const float*)d_in[19];
    float* out = (float*)d_out;

    float *p_qkvp, *p_scores, *p_maskbias;
    cudaGetSymbolAddress((void**)&p_qkvp,     g_qkvp);
    cudaGetSymbolAddress((void**)&p_scores,   g_scores);
    cudaGetSymbolAddress((void**)&p_maskbias, g_maskbias);

    static int smem_set = 0;
    if (!smem_set) {
        cudaFuncSetAttribute(bias_softmax_kernel,
                             cudaFuncAttributeMaxDynamicSharedMemorySize, ZDYN_BYTES);
        smem_set = 1;
    }

    const float scale = 0.17677669529663687f;  // 1/sqrt(32)

    // 1: fused prep (bf16 s_n + bf16 Wall + pair precompute + coords + maskbias)
    prep_fused<<<S_LEN + 129 + 8 + 8, 128>>>(s, ln_s_g, ln_s_b, ln_z_g, ln_z_b, W_pair,
                                             Wq, Wk, Wv, Wvp, bvp, rigids, mask);

    // 2: qkvp = s_n @ Wall^T + bias832 (bf16 tensor-core mma, fp32 out)
    {
        dim3 grid(QKVP_N / 64, S_LEN / 64, 1);  // 13 x 16
        qkvp_mma_kernel<<<grid, 256>>>();
    }
    // 3: qk scores per head (layout [i][h][j]); mask folded via bias
    {
        dim3 grid(S_LEN / BN, S_LEN / BM, NH);
        gemm_nt<<<grid, 256>>>(p_qkvp, QKVP_N, 32,
                               p_qkvp + 256, QKVP_N, 32,
                               p_scores, NH * S_LEN, S_LEN,
                               S_LEN, S_LEN, HD, scale, p_maskbias);
    }

    // 4: the big fused z pass (profiled slot)
    bias_softmax_kernel<<<S_LEN, 256, ZDYN_BYTES>>>(z);

    vp_kernel<<<4, 256>>>();
    point_kernel<<<S_LEN, 256>>>(mask);

    // split-K attn @ v
    {
        dim3 grid(4, S_LEN / 64, NH);
        attnv_kernel<<<grid, 256>>>();
    }

    // fused output epilogue
    {
        dim3 grid(CS / BN, S_LEN / BM, 1);
        fused_out_kernel<<<grid, 256>>>(s, Wo, bo, W_po, b_po, w_scalar, w_point, out);
    }
}

// round 13
// speedup vs baseline: 1.3345x; 1.1468x over previous
#include <cuda_runtime.h>
#include <cuda_bf16.h>
#include <math.h>

#define S_LEN 1024
#define CS 384
#define CZ 128
#define CH 256
#define NH 8
#define HD 32
#define PV 8
#define QKVP_N 832   // 256+256+256+64
#define INFV 100000.0f
#define SC_PITCH 1036

#define ZTILE_ROWS 32
#define ZTILE_FLOATS (ZTILE_ROWS * CZ)   // 4096 floats = 16KB
#define NSTAGES 4
#define NTILES (S_LEN / ZTILE_ROWS)      // 32
#define ZDYN_BYTES (NSTAGES * ZTILE_FLOATS * 4)  // 65536

// ---------------- scratch (__device__ globals, no allocation) ----------------
__device__ __align__(16) __nv_bfloat16 g_sn_bf[S_LEN * CS];
__device__ __align__(16) __nv_bfloat16 g_Wall_bf[QKVP_N * CS];
__device__ __align__(16) float g_qkvp[S_LEN * QKVP_N];
__device__ __align__(16) __nv_bfloat16 g_qkvp_bf[S_LEN * QKVP_N];
__device__ __align__(16) __nv_bfloat16 g_vT_bf[CH * S_LEN];          // [d][j]
__device__ __align__(16) float g_scores[S_LEN * NH * S_LEN];          // [i][h][j] fp32
__device__ __align__(16) __nv_bfloat16 g_attn_bf[S_LEN * NH * S_LEN]; // [i][h][j] bf16
__device__ __align__(16) float g_aop[4 * S_LEN * CH];                 // split-K partials
__device__ __align__(16) float g_bias832[QKVP_N];
__device__ __align__(16) float g_gw[NH * CZ];
__device__ float g_gwsum[NH];
__device__ float g_bw[NH];
__device__ __align__(16) float g_maskbias[S_LEN];
__device__ __align__(16) float g_coords[S_LEN * 4];
__device__ __align__(16) float g_vp[S_LEN * 24];
__device__ __align__(16) float g_attpts[S_LEN * 24];

// ---------------- packed f32x2 helpers (sm_103a FFMA2) ----------------
__device__ __forceinline__ unsigned long long pk(float x, float y) {
    float2 v = make_float2(x, y);
    return *reinterpret_cast<unsigned long long*>(&v);
}
__device__ __forceinline__ float2 upk(unsigned long long u) {
    return *reinterpret_cast<float2*>(&u);
}
__device__ __forceinline__ unsigned long long fma2(unsigned long long a,
                                                   unsigned long long b,
                                                   unsigned long long c) {
    unsigned long long d;
    asm("fma.rn.f32x2 %0, %1, %2, %3;" : "=l"(d) : "l"(a), "l"(b), "l"(c));
    return d;
}
__device__ __forceinline__ unsigned long long add2(unsigned long long a,
                                                   unsigned long long b) {
    unsigned long long d;
    asm("add.rn.f32x2 %0, %1, %2;" : "=l"(d) : "l"(a), "l"(b));
    return d;
}

#define MMA16816(c0, c1, c2, c3, a0, a1, a2, a3, b0, b1)                     \
    asm volatile(                                                            \
        "mma.sync.aligned.m16n8k16.row.col.f32.bf16.bf16.f32 "               \
        "{%0,%1,%2,%3}, {%4,%5,%6,%7}, {%8,%9}, {%0,%1,%2,%3};"              \
        : "+f"(c0), "+f"(c1), "+f"(c2), "+f"(c3)                             \
        : "r"(a0), "r"(a1), "r"(a2), "r"(a3), "r"(b0), "r"(b1))

// ---------------- fused prep ----------------
__global__ void prep_fused(const float* __restrict__ s,
                           const float* __restrict__ ln_s_g, const float* __restrict__ ln_s_b,
                           const float* __restrict__ ln_z_g, const float* __restrict__ ln_z_b,
                           const float* __restrict__ W_pair,
                           const float* __restrict__ Wq, const float* __restrict__ Wk,
                           const float* __restrict__ Wv, const float* __restrict__ Wvp,
                           const float* __restrict__ bvp, const float* __restrict__ rigids,
                           const float* __restrict__ mask) {
    int b = blockIdx.x;
    int t = threadIdx.x;  // 128
    __shared__ float red[128];
    if (b < S_LEN) {
        const float* row = s + (long)b * CS;
        float x0 = row[t], x1 = row[t + 128], x2 = row[t + 256];
        red[t] = x0 + x1 + x2; __syncthreads();
        for (int st = 64; st > 0; st >>= 1) { if (t < st) red[t] += red[t + st]; __syncthreads(); }
        float mean = red[0] * (1.0f / CS);
        __syncthreads();
        float d0 = x0 - mean, d1 = x1 - mean, d2 = x2 - mean;
        red[t] = d0 * d0 + d1 * d1 + d2 * d2; __syncthreads();
        for (int st = 64; st > 0; st >>= 1) { if (t < st) red[t] += red[t + st]; __syncthreads(); }
        float r = rsqrtf(red[0] * (1.0f / CS) + 1e-5f);
        __nv_bfloat16* o = g_sn_bf + (long)b * CS;
        o[t]       = __float2bfloat16(d0 * r * ln_s_g[t]       + ln_s_b[t]);
        o[t + 128] = __float2bfloat16(d1 * r * ln_s_g[t + 128] + ln_s_b[t + 128]);
        o[t + 256] = __float2bfloat16(d2 * r * ln_s_g[t + 256] + ln_s_b[t + 256]);
    } else if (b < S_LEN + 128) {
        int t2 = (b - S_LEN) * 128 + t;
        for (int idx = t2; idx < QKVP_N * CS; idx += 128 * 128) {
            int r = idx / CS, c = idx % CS;
            float v;
            if (r < 256)      v = Wq[r * CS + c];
            else if (r < 512) v = Wk[(r - 256) * CS + c];
            else if (r < 768) v = Wv[(r - 512) * CS + c];
            else              v = Wvp[(r - 768) * CS + c];
            g_Wall_bf[idx] = __float2bfloat16(v);
        }
        if (t2 < QKVP_N) g_bias832[t2] = (t2 >= 768) ? bvp[t2 - 768] : 0.0f;
    } else if (b == S_LEN + 128) {
        int c = t;  // 128
        for (int h = 0; h < NH; h++) {
            float w = W_pair[h * CZ + c];
            float gv = ln_z_g[c] * w;
            g_gw[h * CZ + c] = gv;
            red[c] = gv; __syncthreads();
            for (int st = 64; st > 0; st >>= 1) { if (c < st) red[c] += red[c + st]; __syncthreads(); }
            if (c == 0) g_gwsum[h] = red[0];
            __syncthreads();
            red[c] = ln_z_b[c] * w; __syncthreads();
            for (int st = 64; st > 0; st >>= 1) { if (c < st) red[c] += red[c + st]; __syncthreads(); }
            if (c == 0) g_bw[h] = red[0];
            __syncthreads();
        }
    } else if (b < S_LEN + 129 + 8) {
        int i = (b - (S_LEN + 129)) * 128 + t;
        if (i < S_LEN) {
            const float* rg = rigids + i * 16;
            float4 c;
            c.x = rg[3]; c.y = rg[7]; c.z = rg[11]; c.w = 0.0f;
            ((float4*)g_coords)[i] = c;
        }
    } else {
        int i = (b - (S_LEN + 137)) * 128 + t;
        if (i < S_LEN) {
            const float inv_scale = 5.656854249492381f;  // sqrt(32)
            g_maskbias[i] = INFV * (mask[i] - 1.0f) * inv_scale;
        }
    }
}

// ---------------- qkvp via bf16 mma; emits fp32 + bf16 + vT ----------------
#define AS_STRIDE 24
__global__ __launch_bounds__(256) void qkvp_mma_kernel() {
    __shared__ __nv_bfloat16 As[64][AS_STRIDE];
    __shared__ __nv_bfloat16 Bs[64][AS_STRIDE];
    int tid = threadIdx.x;
    int warp = tid >> 5, lane = tid & 31;
    int m0 = blockIdx.y * 64, n0 = blockIdx.x * 64;
    int wm = (warp & 3) * 16, wn = (warp >> 2) * 32;
    int g = lane >> 2, t = lane & 3;

    float c[4][4] = {};
    for (int kt = 0; kt < CS; kt += 16) {
#pragma unroll
        for (int p = 0; p < 2; p++) {
            int idx = tid + p * 256;
            int row = idx >> 3, cc = (idx & 7) * 2;
            *(unsigned*)&As[row][cc] =
                *(const unsigned*)&g_sn_bf[(long)(m0 + row) * CS + kt + cc];
            *(unsigned*)&Bs[row][cc] =
                *(const unsigned*)&g_Wall_bf[(long)(n0 + row) * CS + kt + cc];
        }
        __syncthreads();
        unsigned a0 = *(const unsigned*)&As[wm + g][t * 2];
        unsigned a1 = *(const unsigned*)&As[wm + g + 8][t * 2];
        unsigned a2 = *(const unsigned*)&As[wm + g][t * 2 + 8];
        unsigned a3 = *(const unsigned*)&As[wm + g + 8][t * 2 + 8];
#pragma unroll
        for (int f = 0; f < 4; f++) {
            unsigned b0 = *(const unsigned*)&Bs[wn + f * 8 + g][t * 2];
            unsigned b1 = *(const unsigned*)&Bs[wn + f * 8 + g][t * 2 + 8];
            MMA16816(c[f][0], c[f][1], c[f][2], c[f][3], a0, a1, a2, a3, b0, b1);
        }
        __syncthreads();
    }
#pragma unroll
    for (int f = 0; f < 4; f++) {
        int col = n0 + wn + f * 8 + t * 2;
        float b0 = g_bias832[col], b1 = g_bias832[col + 1];
        int row0 = m0 + wm + g, row1 = row0 + 8;
        float v00 = c[f][0] + b0, v01 = c[f][1] + b1;
        float v10 = c[f][2] + b0, v11 = c[f][3] + b1;
        *(float2*)&g_qkvp[(long)row0 * QKVP_N + col] = make_float2(v00, v01);
        *(float2*)&g_qkvp[(long)row1 * QKVP_N + col] = make_float2(v10, v11);
        *(__nv_bfloat162*)&g_qkvp_bf[(long)row0 * QKVP_N + col] = __floats2bfloat162_rn(v00, v01);
        *(__nv_bfloat162*)&g_qkvp_bf[(long)row1 * QKVP_N + col] = __floats2bfloat162_rn(v10, v11);
        if (col >= 512 && col < 768) {
            int d = col - 512;
            g_vT_bf[(long)d * S_LEN + row0]       = __float2bfloat16(v00);
            g_vT_bf[(long)(d + 1) * S_LEN + row0] = __float2bfloat16(v01);
            g_vT_bf[(long)d * S_LEN + row1]       = __float2bfloat16(v10);
            g_vT_bf[(long)(d + 1) * S_LEN + row1] = __float2bfloat16(v11);
        }
    }
}

// ---------------- qk scores via bf16 mma: per head, K=32 staged once ----------------
__global__ __launch_bounds__(256) void qk_mma_kernel() {
    __shared__ __nv_bfloat16 As[64][40];
    __shared__ __nv_bfloat16 Bs[64][40];
    int tid = threadIdx.x;
    int warp = tid >> 5, lane = tid & 31;
    int h = blockIdx.z;
    int m0 = blockIdx.y * 64, n0 = blockIdx.x * 64;
    int wm = (warp & 3) * 16, wn = (warp >> 2) * 32;
    int g = lane >> 2, t = lane & 3;

    const __nv_bfloat16* qb = g_qkvp_bf + h * 32;        // q
    const __nv_bfloat16* kb = g_qkvp_bf + 256 + h * 32;  // k
#pragma unroll
    for (int p = 0; p < 4; p++) {
        int idx = tid + p * 256;
        int row = idx >> 4, cc = (idx & 15) * 2;
        *(unsigned*)&As[row][cc] = *(const unsigned*)&qb[(long)(m0 + row) * QKVP_N + cc];
        *(unsigned*)&Bs[row][cc] = *(const unsigned*)&kb[(long)(n0 + row) * QKVP_N + cc];
    }
    __syncthreads();
    float c[4][4] = {};
#pragma unroll
    for (int ks = 0; ks < 2; ks++) {
        unsigned a0 = *(const unsigned*)&As[wm + g][ks * 16 + t * 2];
        unsigned a1 = *(const unsigned*)&As[wm + g + 8][ks * 16 + t * 2];
        unsigned a2 = *(const unsigned*)&As[wm + g][ks * 16 + t * 2 + 8];
        unsigned a3 = *(const unsigned*)&As[wm + g + 8][ks * 16 + t * 2 + 8];
#pragma unroll
        for (int f = 0; f < 4; f++) {
            unsigned b0 = *(const unsigned*)&Bs[wn + f * 8 + g][ks * 16 + t * 2];
            unsigned b1 = *(const unsigned*)&Bs[wn + f * 8 + g][ks * 16 + t * 2 + 8];
            MMA16816(c[f][0], c[f][1], c[f][2], c[f][3], a0, a1, a2, a3, b0, b1);
        }
    }
    const float scale = 0.17677669529663687f;
#pragma unroll
    for (int f = 0; f < 4; f++) {
        int col = n0 + wn + f * 8 + t * 2;
        float mb0 = g_maskbias[col], mb1 = g_maskbias[col + 1];
        int row0 = m0 + wm + g, row1 = row0 + 8;
        *(float2*)&g_scores[((long)row0 * NH + h) * S_LEN + col] =
            make_float2((c[f][0] + mb0) * scale, (c[f][1] + mb1) * scale);
        *(float2*)&g_scores[((long)row1 * NH + h) * S_LEN + col] =
            make_float2((c[f][2] + mb0) * scale, (c[f][3] + mb1) * scale);
    }
}

// ---------------- attn @ v via bf16 mma: split-K=4, A=attn_bf, B=vT_bf ----------------
__global__ __launch_bounds__(256) void attnv_mma_kernel() {
    __shared__ __nv_bfloat16 As[64][72];
    __shared__ __nv_bfloat16 Bs[32][72];
    int tid = threadIdx.x;
    int warp = tid >> 5, lane = tid & 31;
    int ks = blockIdx.x;
    int m0 = blockIdx.y * 64;
    int h = blockIdx.z;
    int wm = (warp & 3) * 16, wn = (warp >> 2) * 16;
    int g = lane >> 2, t = lane & 3;
    const __nv_bfloat16* A = g_attn_bf + (long)h * S_LEN;  // attn[i][h][j]

    float c[2][4] = {};
    int k0 = ks * 256;
    for (int kt = 0; kt < 4; kt++) {
#pragma unroll
        for (int p = 0; p < 8; p++) {
            int idx = tid + p * 256;
            int row = idx >> 5, cc = (idx & 31) * 2;
            *(unsigned*)&As[row][cc] =
                *(const unsigned*)&A[(long)(m0 + row) * (NH * S_LEN) + k0 + kt * 64 + cc];
        }
#pragma unroll
        for (int p = 0; p < 4; p++) {
            int idx = tid + p * 256;
            int row = idx >> 5, cc = (idx & 31) * 2;
            *(unsigned*)&Bs[row][cc] =
                *(const unsigned*)&g_vT_bf[(long)(h * 32 + row) * S_LEN + k0 + kt * 64 + cc];
        }
        __syncthreads();
#pragma unroll
        for (int ko = 0; ko < 4; ko++) {
            unsigned a0 = *(const unsigned*)&As[wm + g][ko * 16 + t * 2];
            unsigned a1 = *(const unsigned*)&As[wm + g + 8][ko * 16 + t * 2];
            unsigned a2 = *(const unsigned*)&As[wm + g][ko * 16 + t * 2 + 8];
            unsigned a3 = *(const unsigned*)&As[wm + g + 8][ko * 16 + t * 2 + 8];
#pragma unroll
            for (int f = 0; f < 2; f++) {
                unsigned b0 = *(const unsigned*)&Bs[wn + f * 8 + g][ko * 16 + t * 2];
                unsigned b1 = *(const unsigned*)&Bs[wn + f * 8 + g][ko * 16 + t * 2 + 8];
                MMA16816(c[f][0], c[f][1], c[f][2], c[f][3], a0, a1, a2, a3, b0, b1);
            }
        }
        __syncthreads();
    }
    float* C = g_aop + (long)ks * (S_LEN * CH);
#pragma unroll
    for (int f = 0; f < 2; f++) {
        int col = h * 32 + wn + f * 8 + t * 2;
        int row0 = m0 + wm + g, row1 = row0 + 8;
        *(float2*)&C[(long)row0 * CH + col] = make_float2(c[f][0], c[f][1]);
        *(float2*)&C[(long)row1 * CH + col] = make_float2(c[f][2], c[f][3]);
    }
}

// ---------------- fused z-pass (frozen R5 config) ----------------
__global__ __launch_bounds__(256) void bias_softmax_kernel(const float* __restrict__ z) {
    extern __shared__ __align__(16) float zbuf[];  // 64KB
    __shared__ float sc[NH * SC_PITCH];

    int i = blockIdx.x;
    int tid = threadIdx.x;  // 256
    int w = tid >> 5, lane = tid & 31;
    int sub = lane >> 4, r16 = lane & 15;

    unsigned long long wa01[NH], wa23[NH], wc01[NH], wc23[NH];
#pragma unroll
    for (int h = 0; h < NH; h++) {
        float4 wa = *(const float4*)(g_gw + h * CZ + r16 * 4);
        float4 wc = *(const float4*)(g_gw + h * CZ + 64 + r16 * 4);
        wa01[h] = pk(wa.x, wa.y); wa23[h] = pk(wa.z, wa.w);
        wc01[h] = pk(wc.x, wc.y); wc23[h] = pk(wc.z, wc.w);
    }
    int h_own = (r16 >> 1) & 7;
    float gws_own = g_gwsum[h_own];
    float bw_own  = g_bw[h_own];
    bool wr_lane = ((r16 & 1) == 0);
    bool b3 = (r16 & 8) != 0, b2 = (r16 & 4) != 0, b1 = (r16 & 2) != 0;

    const float* zbase = z + ((long)i << 17);

#define ISSUE_TILE(T)                                                                   \
    do {                                                                                \
        if ((T) < NTILES) {                                                             \
            const float4* src = (const float4*)(zbase + (long)(T) * ZTILE_FLOATS);      \
            float4* dst = (float4*)(zbuf + ((T) % NSTAGES) * ZTILE_FLOATS);             \
            _Pragma("unroll")                                                           \
            for (int p = 0; p < 4; p++) {                                               \
                int c = tid + p * 256;                                                  \
                unsigned saddr = (unsigned)__cvta_generic_to_shared(dst + c);           \
                asm volatile("cp.async.cg.shared.global [%0], [%1], 16;"                \
                             :: "r"(saddr), "l"(src + c));                              \
            }                                                                           \
        }                                                                               \
        asm volatile("cp.async.commit_group;" ::);                                      \
    } while (0)

    ISSUE_TILE(0); ISSUE_TILE(1); ISSUE_TILE(2);

    for (int t = 0; t < NTILES; t++) {
        asm volatile("cp.async.wait_group %0;" :: "n"(2));
        __syncthreads();
        const float* sb = zbuf + (t % NSTAGES) * ZTILE_FLOATS;
#pragma unroll
        for (int it = 0; it < 2; it++) {
            int lrow = it * 16 + 2 * w + sub;
            const float4* zr = (const float4*)(sb + lrow * CZ);
            float4 A0 = zr[r16];
            float4 A1 = zr[16 + r16];
            unsigned long long za01 = pk(A0.x, A0.y), za23 = pk(A0.z, A0.w);
            unsigned long long zc01 = pk(A1.x, A1.y), zc23 = pk(A1.z, A1.w);
            unsigned long long sz2  = add2(add2(za01, za23), add2(zc01, zc23));
            unsigned long long szz2 = fma2(za01, za01, fma2(za23, za23,
                                      fma2(zc01, zc01, fma2(zc23, zc23, 0ull))));
            float dot[NH];
#pragma unroll
            for (int h = 0; h < NH; h++) {
                unsigned long long d2 = fma2(za01, wa01[h], fma2(za23, wa23[h],
                                        fma2(zc01, wc01[h], fma2(zc23, wc23[h], 0ull))));
                float2 d = upk(d2);
                dot[h] = d.x + d.y;
            }
            float2 s2 = upk(sz2);  float sz  = s2.x + s2.y;
            float2 q2 = upk(szz2); float szz = q2.x + q2.y;

#pragma unroll
            for (int o = 8; o >= 1; o >>= 1) {
                sz  += __shfl_xor_sync(0xffffffffu, sz, o);
                szz += __shfl_xor_sync(0xffffffffu, szz, o);
            }
#pragma unroll
            for (int k = 0; k < 8; k++) dot[k] += __shfl_xor_sync(0xffffffffu, dot[k], 8);
            float y0 = b3 ? dot[4] : dot[0];
            float y1 = b3 ? dot[5] : dot[1];
            float y2 = b3 ? dot[6] : dot[2];
            float y3 = b3 ? dot[7] : dot[3];
            y0 += __shfl_xor_sync(0xffffffffu, y0, 4);
            y1 += __shfl_xor_sync(0xffffffffu, y1, 4);
            y2 += __shfl_xor_sync(0xffffffffu, y2, 4);
            y3 += __shfl_xor_sync(0xffffffffu, y3, 4);
            float t0 = b2 ? y2 : y0;
            float t1 = b2 ? y3 : y1;
            t0 += __shfl_xor_sync(0xffffffffu, t0, 2);
            t1 += __shfl_xor_sync(0xffffffffu, t1, 2);
            float f = b1 ? t1 : t0;
            f += __shfl_xor_sync(0xffffffffu, f, 1);

            float mean = sz * (1.0f / CZ);
            float var = szz * (1.0f / CZ) - mean * mean;
            float r = rsqrtf(var + 1e-5f);
            if (wr_lane)
                sc[h_own * SC_PITCH + t * ZTILE_ROWS + lrow] =
                    r * f - r * mean * gws_own + bw_own;
        }
        __syncthreads();
        ISSUE_TILE(t + 3);
    }
#undef ISSUE_TILE
    __syncthreads();

    // softmax: warp w owns head w; attn out -> bf16
    float* srw = sc + w * SC_PITCH;
    const float* qk = g_scores + (long)i * (NH * S_LEN) + (long)w * S_LEN;
    float m = -1e30f;
    for (int jj = lane; jj < S_LEN; jj += 32) {
        float val = qk[jj] + srw[jj];
        srw[jj] = val;
        m = fmaxf(m, val);
    }
#pragma unroll
    for (int o = 16; o > 0; o >>= 1) m = fmaxf(m, __shfl_xor_sync(0xffffffffu, m, o));
    float ssum = 0.0f;
    for (int jj = lane; jj < S_LEN; jj += 32) {
        float e = __expf(srw[jj] - m);
        srw[jj] = e;
        ssum += e;
    }
#pragma unroll
    for (int o = 16; o > 0; o >>= 1) ssum += __shfl_xor_sync(0xffffffffu, ssum, o);
    float rinv = 1.0f / ssum;
    __nv_bfloat16* outp = g_attn_bf + (long)i * (NH * S_LEN) + (long)w * S_LEN;
    for (int jj = lane; jj < S_LEN; jj += 32) outp[jj] = __float2bfloat16(srw[jj] * rinv);
}

// ---------------- point branch ----------------
__global__ void vp_kernel() {
    int i = blockIdx.x * blockDim.x + threadIdx.x;
    if (i >= S_LEN) return;
    float4 c = ((const float4*)g_coords)[i];
    const float* row = g_qkvp + (long)i * QKVP_N + 768;
#pragma unroll
    for (int h = 0; h < NH; h++) {
        float sm = 0.0f;
#pragma unroll
        for (int p = 0; p < PV; p++) sm += row[h * PV + p];
        g_vp[i * 24 + h * 3 + 0] = sm * c.x;
        g_vp[i * 24 + h * 3 + 1] = sm * c.y;
        g_vp[i * 24 + h * 3 + 2] = sm * c.z;
    }
}

__global__ __launch_bounds__(256) void point_kernel(const float* __restrict__ mask) {
    int i = blockIdx.x;
    int tid = threadIdx.x;  // 256
    __shared__ float svp[256 * 25];
    __shared__ float4 sco[256];
    __shared__ float sred[8 * 25];

    float4 ci = ((const float4*)g_coords)[i];
    float mi = mask[i];
    float acc[24] = {};
    float sw = 0.0f;

    for (int jt = 0; jt < 4; jt++) {
        int jbase = jt * 256;
        for (int idx = tid; idx < 256 * 24; idx += 256)
            svp[(idx / 24) * 25 + (idx % 24)] = g_vp[jbase * 24 + idx];
        sco[tid] = ((const float4*)g_coords)[jbase + tid];
        __syncthreads();
        int jl = tid;
        float4 cj = sco[jl];
        float dx = ci.x - cj.x, dy = ci.y - cj.y, dz = ci.z - cj.z;
        float dist = sqrtf(dx * dx + dy * dy + dz * dz + 1e-12f);
        float wgt = __expf(-dist * 0.1f) * mi * mask[jbase + jl];
        sw += wgt;
#pragma unroll
        for (int p = 0; p < 24; p++) acc[p] = fmaf(wgt, svp[jl * 25 + p], acc[p]);
        __syncthreads();
    }

    int wr = tid >> 5, lane = tid & 31;
#pragma unroll
    for (int o = 16; o > 0; o >>= 1) {
        sw += __shfl_xor_sync(0xffffffffu, sw, o);
#pragma unroll
        for (int p = 0; p < 24; p++) acc[p] += __shfl_xor_sync(0xffffffffu, acc[p], o);
    }
    if (lane == 0) {
#pragma unroll
        for (int p = 0; p < 24; p++) sred[wr * 25 + p] = acc[p];
        sred[wr * 25 + 24] = sw;
    }
    __syncthreads();
    if (tid < 24) {
        float s = 0.0f, swt = 0.0f;
#pragma unroll
        for (int k = 0; k < 8; k++) { s += sred[k * 25 + tid]; swt += sred[k * 25 + 24]; }
        g_attpts[i * 24 + tid] = s / (swt + 1e-8f);
    }
}

// ---------------- fused output epilogue ----------------
#define BM 64
#define BN 64
#define BK 16
__global__ __launch_bounds__(256) void fused_out_kernel(const float* __restrict__ s,
                                                        const float* __restrict__ Wo,
                                                        const float* __restrict__ bo,
                                                        const float* __restrict__ W_po,
                                                        const float* __restrict__ b_po,
                                                        const float* __restrict__ w_scalar,
                                                        const float* __restrict__ w_point,
                                                        float* __restrict__ out) {
    int m0 = blockIdx.y * BM;
    int n0 = blockIdx.x * BN;
    __shared__ float As[BK][BM + 1];
    __shared__ float Bs[BK][BN + 1];
    int tid = threadIdx.x;
    int tx = tid % 16, ty = tid / 16;
    float acc1[4][4] = {};
    for (int kt = 0; kt < CH; kt += BK) {
#pragma unroll
        for (int p = 0; p < 4; p++) {
            int idx = p * 256 + tid;
            int ml = idx / BK, kl = idx % BK;
            long off = (long)(m0 + ml) * CH + kt + kl;
            As[kl][ml] = g_aop[off] + g_aop[S_LEN * CH + off] +
                         g_aop[2 * S_LEN * CH + off] + g_aop[3 * S_LEN * CH + off];
        }
#pragma unroll
        for (int p = 0; p < 4; p++) {
            int idx = p * 256 + tid;
            int nl = idx / BK, kl = idx % BK;
            Bs[kl][nl] = Wo[(long)(n0 + nl) * CH + kt + kl];
        }
        __syncthreads();
#pragma unroll
        for (int k = 0; k < BK; k++) {
            float a[4], b[4];
#pragma unroll
            for (int i = 0; i < 4; i++) a[i] = As[k][ty * 4 + i];
#pragma unroll
            for (int j = 0; j < 4; j++) b[j] = Bs[k][tx * 4 + j];
#pragma unroll
            for (int i = 0; i < 4; i++)
#pragma unroll
                for (int j = 0; j < 4; j++) acc1[i][j] = fmaf(a[i], b[j], acc1[i][j]);
        }
        __syncthreads();
    }
    __shared__ float As2[BM][25];
    __shared__ float Bs2[BN][25];
    for (int idx = tid; idx < BM * 24; idx += 256)
        As2[idx / 24][idx % 24] = g_attpts[(long)(m0 + idx / 24) * 24 + idx % 24];
    for (int idx = tid; idx < BN * 24; idx += 256)
        Bs2[idx / 24][idx % 24] = W_po[(long)(n0 + idx / 24) * 24 + idx % 24];
    __syncthreads();
    float acc2[4][4] = {};
#pragma unroll
    for (int k = 0; k < 24; k++) {
        float a[4], b[4];
#pragma unroll
        for (int i = 0; i < 4; i++) a[i] = As2[ty * 4 + i][k];
#pragma unroll
        for (int j = 0; j < 4; j++) b[j] = Bs2[tx * 4 + j][k];
#pragma unroll
        for (int i = 0; i < 4; i++)
#pragma unroll
            for (int j = 0; j < 4; j++) acc2[i][j] = fmaf(a[i], b[j], acc2[i][j]);
    }
    float ws = *w_scalar, wp = *w_point;
#pragma unroll
    for (int i = 0; i < 4; i++) {
        int m = m0 + ty * 4 + i;
#pragma unroll
        for (int j = 0; j < 4; j++) {
            int n = n0 + tx * 4 + j;
            out[(long)m * CS + n] = s[(long)m * CS + n]
                + ws * (acc1[i][j] + bo[n])
                + wp * (acc2[i][j] + b_po[n]);
        }
    }
}

// ---------------- launch ----------------
extern "C" void kernel_launch(void* const* d_in, const int* in_sizes, int n_in,
                              void* d_out, int out_size) {
    const float* s       = (const float*)d_in[0];
    const float* z       = (const float*)d_in[1];
    const float* rigids  = (const float*)d_in[2];
    const float* mask    = (const float*)d_in[3];
    const float* ln_s_g  = (const float*)d_in[4];
    const float* ln_s_b  = (const float*)d_in[5];
    const float* ln_z_g  = (const float*)d_in[6];
    const float* ln_z_b  = (const float*)d_in[7];
    const float* Wq      = (const float*)d_in[8];
    const float* Wk      = (const float*)d_in[9];
    const float* Wv      = (const float*)d_in[10];
    const float* W_pair  = (const float*)d_in[11];
    const float* Wo      = (const float*)d_in[12];
    const float* bo      = (const float*)d_in[13];
    const float* Wvp     = (const float*)d_in[14];
    const float* bvp     = (const float*)d_in[15];
    const float* W_po    = (const float*)d_in[16];
    const float* b_po    = (const float*)d_in[17];
    const float* w_scalar= (const float*)d_in[18];
    const float* w_point = (const float*)d_in[19];
    float* out = (float*)d_out;

    static int smem_set = 0;
    if (!smem_set) {
        cudaFuncSetAttribute(bias_softmax_kernel,
                             cudaFuncAttributeMaxDynamicSharedMemorySize, ZDYN_BYTES);
        smem_set = 1;
    }

    // 1: fused prep
    prep_fused<<<S_LEN + 129 + 8 + 8, 128>>>(s, ln_s_g, ln_s_b, ln_z_g, ln_z_b, W_pair,
                                             Wq, Wk, Wv, Wvp, bvp, rigids, mask);

    // 2: qkvp (tensor core) -> fp32 + bf16 + vT
    {
        dim3 grid(QKVP_N / 64, S_LEN / 64, 1);  // 13 x 16
        qkvp_mma_kernel<<<grid, 256>>>();
    }
    // 3: qk scores (tensor core, mask folded)
    {
        dim3 grid(S_LEN / 64, S_LEN / 64, NH);  // 16 x 16 x 8
        qk_mma_kernel<<<grid, 256>>>();
    }

    // 4: the big fused z pass
    bias_softmax_kernel<<<S_LEN, 256, ZDYN_BYTES>>>(z);

    vp_kernel<<<4, 256>>>();
    point_kernel<<<S_LEN, 256>>>(mask);

    // attn @ v (tensor core, split-K)
    {
        dim3 grid(4, S_LEN / 64, NH);
        attnv_mma_kernel<<<grid, 256>>>();
    }

    // fused output epilogue
    {
        dim3 grid(CS / BN, S_LEN / BM, 1);
        fused_out_kernel<<<grid, 256>>>(s, Wo, bo, W_po, b_po, w_scalar, w_point, out);
    }
}

// round 14
// speedup vs baseline: 1.4116x; 1.0578x over previous
#include <cuda_runtime.h>
#include <cuda_bf16.h>
#include <math.h>

#define S_LEN 1024
#define CS 384
#define CZ 128
#define CH 256
#define NH 8
#define HD 32
#define PV 8
#define QKVP_N 832   // 256+256+256+64
#define INFV 100000.0f
#define SC_PITCH 1036

#define ZTILE_ROWS 32
#define ZTILE_FLOATS (ZTILE_ROWS * CZ)   // 4096 floats = 16KB
#define NSTAGES 4
#define NTILES (S_LEN / ZTILE_ROWS)      // 32
#define ZDYN_BYTES (NSTAGES * ZTILE_FLOATS * 4)  // 65536

// ---------------- scratch (__device__ globals, no allocation) ----------------
__device__ __align__(16) __nv_bfloat16 g_sn_bf[S_LEN * CS];
__device__ __align__(16) __nv_bfloat16 g_Wall_bf[QKVP_N * CS];
__device__ __align__(16) float g_qkvp[S_LEN * QKVP_N];
__device__ __align__(16) __nv_bfloat16 g_qkvp_bf[S_LEN * QKVP_N];
__device__ __align__(16) __nv_bfloat16 g_vT_bf[CH * S_LEN];           // [d][j]
__device__ __align__(16) __nv_bfloat16 g_scores_bf[S_LEN * NH * S_LEN]; // [i][h][j]
__device__ __align__(16) __nv_bfloat16 g_attn_bf[S_LEN * NH * S_LEN];   // [i][h][j]
__device__ __align__(16) float g_aop[4 * S_LEN * CH];                  // split-K partials
__device__ __align__(16) float g_ao[S_LEN * CH];
__device__ __align__(16) float g_bias832[QKVP_N];
__device__ __align__(16) float g_gw[NH * CZ];
__device__ float g_gwsum[NH];
__device__ float g_bw[NH];
__device__ __align__(16) float g_maskbias[S_LEN];
__device__ __align__(16) float g_coords[S_LEN * 4];
__device__ __align__(16) float g_vp[S_LEN * 24];
__device__ __align__(16) float g_attpts[S_LEN * 24];

// ---------------- packed f32x2 helpers ----------------
__device__ __forceinline__ unsigned long long pk(float x, float y) {
    float2 v = make_float2(x, y);
    return *reinterpret_cast<unsigned long long*>(&v);
}
__device__ __forceinline__ float2 upk(unsigned long long u) {
    return *reinterpret_cast<float2*>(&u);
}
__device__ __forceinline__ unsigned long long fma2(unsigned long long a,
                                                   unsigned long long b,
                                                   unsigned long long c) {
    unsigned long long d;
    asm("fma.rn.f32x2 %0, %1, %2, %3;" : "=l"(d) : "l"(a), "l"(b), "l"(c));
    return d;
}
__device__ __forceinline__ unsigned long long add2(unsigned long long a,
                                                   unsigned long long b) {
    unsigned long long d;
    asm("add.rn.f32x2 %0, %1, %2;" : "=l"(d) : "l"(a), "l"(b));
    return d;
}

#define MMA16816(c0, c1, c2, c3, a0, a1, a2, a3, b0, b1)                     \
    asm volatile(                                                            \
        "mma.sync.aligned.m16n8k16.row.col.f32.bf16.bf16.f32 "               \
        "{%0,%1,%2,%3}, {%4,%5,%6,%7}, {%8,%9}, {%0,%1,%2,%3};"              \
        : "+f"(c0), "+f"(c1), "+f"(c2), "+f"(c3)                             \
        : "r"(a0), "r"(a1), "r"(a2), "r"(a3), "r"(b0), "r"(b1))

// ---------------- fused prep ----------------
__global__ void prep_fused(const float* __restrict__ s,
                           const float* __restrict__ ln_s_g, const float* __restrict__ ln_s_b,
                           const float* __restrict__ ln_z_g, const float* __restrict__ ln_z_b,
                           const float* __restrict__ W_pair,
                           const float* __restrict__ Wq, const float* __restrict__ Wk,
                           const float* __restrict__ Wv, const float* __restrict__ Wvp,
                           const float* __restrict__ bvp, const float* __restrict__ rigids,
                           const float* __restrict__ mask) {
    int b = blockIdx.x;
    int t = threadIdx.x;  // 128
    __shared__ float red[128];
    if (b < S_LEN) {
        const float* row = s + (long)b * CS;
        float x0 = row[t], x1 = row[t + 128], x2 = row[t + 256];
        red[t] = x0 + x1 + x2; __syncthreads();
        for (int st = 64; st > 0; st >>= 1) { if (t < st) red[t] += red[t + st]; __syncthreads(); }
        float mean = red[0] * (1.0f / CS);
        __syncthreads();
        float d0 = x0 - mean, d1 = x1 - mean, d2 = x2 - mean;
        red[t] = d0 * d0 + d1 * d1 + d2 * d2; __syncthreads();
        for (int st = 64; st > 0; st >>= 1) { if (t < st) red[t] += red[t + st]; __syncthreads(); }
        float r = rsqrtf(red[0] * (1.0f / CS) + 1e-5f);
        __nv_bfloat16* o = g_sn_bf + (long)b * CS;
        o[t]       = __float2bfloat16(d0 * r * ln_s_g[t]       + ln_s_b[t]);
        o[t + 128] = __float2bfloat16(d1 * r * ln_s_g[t + 128] + ln_s_b[t + 128]);
        o[t + 256] = __float2bfloat16(d2 * r * ln_s_g[t + 256] + ln_s_b[t + 256]);
    } else if (b < S_LEN + 128) {
        int t2 = (b - S_LEN) * 128 + t;
        for (int idx = t2; idx < QKVP_N * CS; idx += 128 * 128) {
            int r = idx / CS, c = idx % CS;
            float v;
            if (r < 256)      v = Wq[r * CS + c];
            else if (r < 512) v = Wk[(r - 256) * CS + c];
            else if (r < 768) v = Wv[(r - 512) * CS + c];
            else              v = Wvp[(r - 768) * CS + c];
            g_Wall_bf[idx] = __float2bfloat16(v);
        }
        if (t2 < QKVP_N) g_bias832[t2] = (t2 >= 768) ? bvp[t2 - 768] : 0.0f;
    } else if (b == S_LEN + 128) {
        int c = t;  // 128
        for (int h = 0; h < NH; h++) {
            float w = W_pair[h * CZ + c];
            float gv = ln_z_g[c] * w;
            g_gw[h * CZ + c] = gv;
            red[c] = gv; __syncthreads();
            for (int st = 64; st > 0; st >>= 1) { if (c < st) red[c] += red[c + st]; __syncthreads(); }
            if (c == 0) g_gwsum[h] = red[0];
            __syncthreads();
            red[c] = ln_z_b[c] * w; __syncthreads();
            for (int st = 64; st > 0; st >>= 1) { if (c < st) red[c] += red[c + st]; __syncthreads(); }
            if (c == 0) g_bw[h] = red[0];
            __syncthreads();
        }
    } else if (b < S_LEN + 129 + 8) {
        int i = (b - (S_LEN + 129)) * 128 + t;
        if (i < S_LEN) {
            const float* rg = rigids + i * 16;
            float4 c;
            c.x = rg[3]; c.y = rg[7]; c.z = rg[11]; c.w = 0.0f;
            ((float4*)g_coords)[i] = c;
        }
    } else {
        int i = (b - (S_LEN + 137)) * 128 + t;
        if (i < S_LEN) {
            const float inv_scale = 5.656854249492381f;  // sqrt(32)
            g_maskbias[i] = INFV * (mask[i] - 1.0f) * inv_scale;
        }
    }
}

// ---------------- qkvp via bf16 mma; emits fp32 + bf16 + vT ----------------
#define AS_STRIDE 24
__global__ __launch_bounds__(256) void qkvp_mma_kernel() {
    __shared__ __nv_bfloat16 As[64][AS_STRIDE];
    __shared__ __nv_bfloat16 Bs[64][AS_STRIDE];
    int tid = threadIdx.x;
    int warp = tid >> 5, lane = tid & 31;
    int m0 = blockIdx.y * 64, n0 = blockIdx.x * 64;
    int wm = (warp & 3) * 16, wn = (warp >> 2) * 32;
    int g = lane >> 2, t = lane & 3;

    float c[4][4] = {};
    for (int kt = 0; kt < CS; kt += 16) {
#pragma unroll
        for (int p = 0; p < 2; p++) {
            int idx = tid + p * 256;
            int row = idx >> 3, cc = (idx & 7) * 2;
            *(unsigned*)&As[row][cc] =
                *(const unsigned*)&g_sn_bf[(long)(m0 + row) * CS + kt + cc];
            *(unsigned*)&Bs[row][cc] =
                *(const unsigned*)&g_Wall_bf[(long)(n0 + row) * CS + kt + cc];
        }
        __syncthreads();
        unsigned a0 = *(const unsigned*)&As[wm + g][t * 2];
        unsigned a1 = *(const unsigned*)&As[wm + g + 8][t * 2];
        unsigned a2 = *(const unsigned*)&As[wm + g][t * 2 + 8];
        unsigned a3 = *(const unsigned*)&As[wm + g + 8][t * 2 + 8];
#pragma unroll
        for (int f = 0; f < 4; f++) {
            unsigned b0 = *(const unsigned*)&Bs[wn + f * 8 + g][t * 2];
            unsigned b1 = *(const unsigned*)&Bs[wn + f * 8 + g][t * 2 + 8];
            MMA16816(c[f][0], c[f][1], c[f][2], c[f][3], a0, a1, a2, a3, b0, b1);
        }
        __syncthreads();
    }
#pragma unroll
    for (int f = 0; f < 4; f++) {
        int col = n0 + wn + f * 8 + t * 2;
        float b0 = g_bias832[col], b1 = g_bias832[col + 1];
        int row0 = m0 + wm + g, row1 = row0 + 8;
        float v00 = c[f][0] + b0, v01 = c[f][1] + b1;
        float v10 = c[f][2] + b0, v11 = c[f][3] + b1;
        *(float2*)&g_qkvp[(long)row0 * QKVP_N + col] = make_float2(v00, v01);
        *(float2*)&g_qkvp[(long)row1 * QKVP_N + col] = make_float2(v10, v11);
        *(__nv_bfloat162*)&g_qkvp_bf[(long)row0 * QKVP_N + col] = __floats2bfloat162_rn(v00, v01);
        *(__nv_bfloat162*)&g_qkvp_bf[(long)row1 * QKVP_N + col] = __floats2bfloat162_rn(v10, v11);
        if (col >= 512 && col < 768) {
            int d = col - 512;
            g_vT_bf[(long)d * S_LEN + row0]       = __float2bfloat16(v00);
            g_vT_bf[(long)(d + 1) * S_LEN + row0] = __float2bfloat16(v01);
            g_vT_bf[(long)d * S_LEN + row1]       = __float2bfloat16(v10);
            g_vT_bf[(long)(d + 1) * S_LEN + row1] = __float2bfloat16(v11);
        }
    }
}

// ---------------- qk scores via bf16 mma: bf16 output ----------------
__global__ __launch_bounds__(256) void qk_mma_kernel() {
    __shared__ __nv_bfloat16 As[64][40];
    __shared__ __nv_bfloat16 Bs[64][40];
    int tid = threadIdx.x;
    int warp = tid >> 5, lane = tid & 31;
    int h = blockIdx.z;
    int m0 = blockIdx.y * 64, n0 = blockIdx.x * 64;
    int wm = (warp & 3) * 16, wn = (warp >> 2) * 32;
    int g = lane >> 2, t = lane & 3;

    const __nv_bfloat16* qb = g_qkvp_bf + h * 32;
    const __nv_bfloat16* kb = g_qkvp_bf + 256 + h * 32;
#pragma unroll
    for (int p = 0; p < 4; p++) {
        int idx = tid + p * 256;
        int row = idx >> 4, cc = (idx & 15) * 2;
        *(unsigned*)&As[row][cc] = *(const unsigned*)&qb[(long)(m0 + row) * QKVP_N + cc];
        *(unsigned*)&Bs[row][cc] = *(const unsigned*)&kb[(long)(n0 + row) * QKVP_N + cc];
    }
    __syncthreads();
    float c[4][4] = {};
#pragma unroll
    for (int ks = 0; ks < 2; ks++) {
        unsigned a0 = *(const unsigned*)&As[wm + g][ks * 16 + t * 2];
        unsigned a1 = *(const unsigned*)&As[wm + g + 8][ks * 16 + t * 2];
        unsigned a2 = *(const unsigned*)&As[wm + g][ks * 16 + t * 2 + 8];
        unsigned a3 = *(const unsigned*)&As[wm + g + 8][ks * 16 + t * 2 + 8];
#pragma unroll
        for (int f = 0; f < 4; f++) {
            unsigned b0 = *(const unsigned*)&Bs[wn + f * 8 + g][ks * 16 + t * 2];
            unsigned b1 = *(const unsigned*)&Bs[wn + f * 8 + g][ks * 16 + t * 2 + 8];
            MMA16816(c[f][0], c[f][1], c[f][2], c[f][3], a0, a1, a2, a3, b0, b1);
        }
    }
    const float scale = 0.17677669529663687f;
#pragma unroll
    for (int f = 0; f < 4; f++) {
        int col = n0 + wn + f * 8 + t * 2;
        float mb0 = g_maskbias[col], mb1 = g_maskbias[col + 1];
        int row0 = m0 + wm + g, row1 = row0 + 8;
        *(__nv_bfloat162*)&g_scores_bf[((long)row0 * NH + h) * S_LEN + col] =
            __floats2bfloat162_rn((c[f][0] + mb0) * scale, (c[f][1] + mb1) * scale);
        *(__nv_bfloat162*)&g_scores_bf[((long)row1 * NH + h) * S_LEN + col] =
            __floats2bfloat162_rn((c[f][2] + mb0) * scale, (c[f][3] + mb1) * scale);
    }
}

// ---------------- attn @ v via bf16 mma: split-K=4 ----------------
__global__ __launch_bounds__(256) void attnv_mma_kernel() {
    __shared__ __nv_bfloat16 As[64][72];
    __shared__ __nv_bfloat16 Bs[32][72];
    int tid = threadIdx.x;
    int warp = tid >> 5, lane = tid & 31;
    int ks = blockIdx.x;
    int m0 = blockIdx.y * 64;
    int h = blockIdx.z;
    int wm = (warp & 3) * 16, wn = (warp >> 2) * 16;
    int g = lane >> 2, t = lane & 3;
    const __nv_bfloat16* A = g_attn_bf + (long)h * S_LEN;

    float c[2][4] = {};
    int k0 = ks * 256;
    for (int kt = 0; kt < 4; kt++) {
#pragma unroll
        for (int p = 0; p < 8; p++) {
            int idx = tid + p * 256;
            int row = idx >> 5, cc = (idx & 31) * 2;
            *(unsigned*)&As[row][cc] =
                *(const unsigned*)&A[(long)(m0 + row) * (NH * S_LEN) + k0 + kt * 64 + cc];
        }
#pragma unroll
        for (int p = 0; p < 4; p++) {
            int idx = tid + p * 256;
            int row = idx >> 5, cc = (idx & 31) * 2;
            *(unsigned*)&Bs[row][cc] =
                *(const unsigned*)&g_vT_bf[(long)(h * 32 + row) * S_LEN + k0 + kt * 64 + cc];
        }
        __syncthreads();
#pragma unroll
        for (int ko = 0; ko < 4; ko++) {
            unsigned a0 = *(const unsigned*)&As[wm + g][ko * 16 + t * 2];
            unsigned a1 = *(const unsigned*)&As[wm + g + 8][ko * 16 + t * 2];
            unsigned a2 = *(const unsigned*)&As[wm + g][ko * 16 + t * 2 + 8];
            unsigned a3 = *(const unsigned*)&As[wm + g + 8][ko * 16 + t * 2 + 8];
#pragma unroll
            for (int f = 0; f < 2; f++) {
                unsigned b0 = *(const unsigned*)&Bs[wn + f * 8 + g][ko * 16 + t * 2];
                unsigned b1 = *(const unsigned*)&Bs[wn + f * 8 + g][ko * 16 + t * 2 + 8];
                MMA16816(c[f][0], c[f][1], c[f][2], c[f][3], a0, a1, a2, a3, b0, b1);
            }
        }
        __syncthreads();
    }
    float* C = g_aop + (long)ks * (S_LEN * CH);
#pragma unroll
    for (int f = 0; f < 2; f++) {
        int col = h * 32 + wn + f * 8 + t * 2;
        int row0 = m0 + wm + g, row1 = row0 + 8;
        *(float2*)&C[(long)row0 * CH + col] = make_float2(c[f][0], c[f][1]);
        *(float2*)&C[(long)row1 * CH + col] = make_float2(c[f][2], c[f][3]);
    }
}

__global__ void combine_ao_kernel() {
    int idx = blockIdx.x * blockDim.x + threadIdx.x;
    if (idx < S_LEN * CH)
        g_ao[idx] = g_aop[idx] + g_aop[S_LEN * CH + idx] +
                    g_aop[2 * S_LEN * CH + idx] + g_aop[3 * S_LEN * CH + idx];
}

// ---------------- fused z-pass (frozen R5 config; softmax reads bf16 scores) ----------------
__global__ __launch_bounds__(256) void bias_softmax_kernel(const float* __restrict__ z) {
    extern __shared__ __align__(16) float zbuf[];  // 64KB
    __shared__ float sc[NH * SC_PITCH];

    int i = blockIdx.x;
    int tid = threadIdx.x;  // 256
    int w = tid >> 5, lane = tid & 31;
    int sub = lane >> 4, r16 = lane & 15;

    unsigned long long wa01[NH], wa23[NH], wc01[NH], wc23[NH];
#pragma unroll
    for (int h = 0; h < NH; h++) {
        float4 wa = *(const float4*)(g_gw + h * CZ + r16 * 4);
        float4 wc = *(const float4*)(g_gw + h * CZ + 64 + r16 * 4);
        wa01[h] = pk(wa.x, wa.y); wa23[h] = pk(wa.z, wa.w);
        wc01[h] = pk(wc.x, wc.y); wc23[h] = pk(wc.z, wc.w);
    }
    int h_own = (r16 >> 1) & 7;
    float gws_own = g_gwsum[h_own];
    float bw_own  = g_bw[h_own];
    bool wr_lane = ((r16 & 1) == 0);
    bool b3 = (r16 & 8) != 0, b2 = (r16 & 4) != 0, b1 = (r16 & 2) != 0;

    const float* zbase = z + ((long)i << 17);

#define ISSUE_TILE(T)                                                                   \
    do {                                                                                \
        if ((T) < NTILES) {                                                             \
            const float4* src = (const float4*)(zbase + (long)(T) * ZTILE_FLOATS);      \
            float4* dst = (float4*)(zbuf + ((T) % NSTAGES) * ZTILE_FLOATS);             \
            _Pragma("unroll")                                                           \
            for (int p = 0; p < 4; p++) {                                               \
                int c = tid + p * 256;                                                  \
                unsigned saddr = (unsigned)__cvta_generic_to_shared(dst + c);           \
                asm volatile("cp.async.cg.shared.global [%0], [%1], 16;"                \
                             :: "r"(saddr), "l"(src + c));                              \
            }                                                                           \
        }                                                                               \
        asm volatile("cp.async.commit_group;" ::);                                      \
    } while (0)

    ISSUE_TILE(0); ISSUE_TILE(1); ISSUE_TILE(2);

    for (int t = 0; t < NTILES; t++) {
        asm volatile("cp.async.wait_group %0;" :: "n"(2));
        __syncthreads();
        const float* sb = zbuf + (t % NSTAGES) * ZTILE_FLOATS;
#pragma unroll
        for (int it = 0; it < 2; it++) {
            int lrow = it * 16 + 2 * w + sub;
            const float4* zr = (const float4*)(sb + lrow * CZ);
            float4 A0 = zr[r16];
            float4 A1 = zr[16 + r16];
            unsigned long long za01 = pk(A0.x, A0.y), za23 = pk(A0.z, A0.w);
            unsigned long long zc01 = pk(A1.x, A1.y), zc23 = pk(A1.z, A1.w);
            unsigned long long sz2  = add2(add2(za01, za23), add2(zc01, zc23));
            unsigned long long szz2 = fma2(za01, za01, fma2(za23, za23,
                                      fma2(zc01, zc01, fma2(zc23, zc23, 0ull))));
            float dot[NH];
#pragma unroll
            for (int h = 0; h < NH; h++) {
                unsigned long long d2 = fma2(za01, wa01[h], fma2(za23, wa23[h],
                                        fma2(zc01, wc01[h], fma2(zc23, wc23[h], 0ull))));
                float2 d = upk(d2);
                dot[h] = d.x + d.y;
            }
            float2 s2 = upk(sz2);  float sz  = s2.x + s2.y;
            float2 q2 = upk(szz2); float szz = q2.x + q2.y;

#pragma unroll
            for (int o = 8; o >= 1; o >>= 1) {
                sz  += __shfl_xor_sync(0xffffffffu, sz, o);
                szz += __shfl_xor_sync(0xffffffffu, szz, o);
            }
#pragma unroll
            for (int k = 0; k < 8; k++) dot[k] += __shfl_xor_sync(0xffffffffu, dot[k], 8);
            float y0 = b3 ? dot[4] : dot[0];
            float y1 = b3 ? dot[5] : dot[1];
            float y2 = b3 ? dot[6] : dot[2];
            float y3 = b3 ? dot[7] : dot[3];
            y0 += __shfl_xor_sync(0xffffffffu, y0, 4);
            y1 += __shfl_xor_sync(0xffffffffu, y1, 4);
            y2 += __shfl_xor_sync(0xffffffffu, y2, 4);
            y3 += __shfl_xor_sync(0xffffffffu, y3, 4);
            float t0 = b2 ? y2 : y0;
            float t1 = b2 ? y3 : y1;
            t0 += __shfl_xor_sync(0xffffffffu, t0, 2);
            t1 += __shfl_xor_sync(0xffffffffu, t1, 2);
            float f = b1 ? t1 : t0;
            f += __shfl_xor_sync(0xffffffffu, f, 1);

            float mean = sz * (1.0f / CZ);
            float var = szz * (1.0f / CZ) - mean * mean;
            float r = rsqrtf(var + 1e-5f);
            if (wr_lane)
                sc[h_own * SC_PITCH + t * ZTILE_ROWS + lrow] =
                    r * f - r * mean * gws_own + bw_own;
        }
        __syncthreads();
        ISSUE_TILE(t + 3);
    }
#undef ISSUE_TILE
    __syncthreads();

    // softmax: warp w owns head w; reads bf16 scores, writes bf16 attn
    float* srw = sc + w * SC_PITCH;
    const __nv_bfloat16* qk = g_scores_bf + (long)i * (NH * S_LEN) + (long)w * S_LEN;
    float m = -1e30f;
    for (int jj = lane; jj < S_LEN; jj += 32) {
        float val = __bfloat162float(qk[jj]) + srw[jj];
        srw[jj] = val;
        m = fmaxf(m, val);
    }
#pragma unroll
    for (int o = 16; o > 0; o >>= 1) m = fmaxf(m, __shfl_xor_sync(0xffffffffu, m, o));
    float ssum = 0.0f;
    for (int jj = lane; jj < S_LEN; jj += 32) {
        float e = __expf(srw[jj] - m);
        srw[jj] = e;
        ssum += e;
    }
#pragma unroll
    for (int o = 16; o > 0; o >>= 1) ssum += __shfl_xor_sync(0xffffffffu, ssum, o);
    float rinv = 1.0f / ssum;
    __nv_bfloat16* outp = g_attn_bf + (long)i * (NH * S_LEN) + (long)w * S_LEN;
    for (int jj = lane; jj < S_LEN; jj += 32) outp[jj] = __float2bfloat16(srw[jj] * rinv);
}

// ---------------- point branch ----------------
__global__ void vp_kernel() {
    int i = blockIdx.x * blockDim.x + threadIdx.x;
    if (i >= S_LEN) return;
    float4 c = ((const float4*)g_coords)[i];
    const float* row = g_qkvp + (long)i * QKVP_N + 768;
#pragma unroll
    for (int h = 0; h < NH; h++) {
        float sm = 0.0f;
#pragma unroll
        for (int p = 0; p < PV; p++) sm += row[h * PV + p];
        g_vp[i * 24 + h * 3 + 0] = sm * c.x;
        g_vp[i * 24 + h * 3 + 1] = sm * c.y;
        g_vp[i * 24 + h * 3 + 2] = sm * c.z;
    }
}

__global__ __launch_bounds__(256) void point_kernel(const float* __restrict__ mask) {
    int i = blockIdx.x;
    int tid = threadIdx.x;  // 256
    __shared__ float svp[256 * 25];
    __shared__ float4 sco[256];
    __shared__ float sred[8 * 25];

    float4 ci = ((const float4*)g_coords)[i];
    float mi = mask[i];
    float acc[24] = {};
    float sw = 0.0f;

    for (int jt = 0; jt < 4; jt++) {
        int jbase = jt * 256;
        for (int idx = tid; idx < 256 * 24; idx += 256)
            svp[(idx / 24) * 25 + (idx % 24)] = g_vp[jbase * 24 + idx];
        sco[tid] = ((const float4*)g_coords)[jbase + tid];
        __syncthreads();
        int jl = tid;
        float4 cj = sco[jl];
        float dx = ci.x - cj.x, dy = ci.y - cj.y, dz = ci.z - cj.z;
        float dist = sqrtf(dx * dx + dy * dy + dz * dz + 1e-12f);
        float wgt = __expf(-dist * 0.1f) * mi * mask[jbase + jl];
        sw += wgt;
#pragma unroll
        for (int p = 0; p < 24; p++) acc[p] = fmaf(wgt, svp[jl * 25 + p], acc[p]);
        __syncthreads();
    }

    int wr = tid >> 5, lane = tid & 31;
#pragma unroll
    for (int o = 16; o > 0; o >>= 1) {
        sw += __shfl_xor_sync(0xffffffffu, sw, o);
#pragma unroll
        for (int p = 0; p < 24; p++) acc[p] += __shfl_xor_sync(0xffffffffu, acc[p], o);
    }
    if (lane == 0) {
#pragma unroll
        for (int p = 0; p < 24; p++) sred[wr * 25 + p] = acc[p];
        sred[wr * 25 + 24] = sw;
    }
    __syncthreads();
    if (tid < 24) {
        float s = 0.0f, swt = 0.0f;
#pragma unroll
        for (int k = 0; k < 8; k++) { s += sred[k * 25 + tid]; swt += sred[k * 25 + 24]; }
        g_attpts[i * 24 + tid] = s / (swt + 1e-8f);
    }
}

// ---------------- fused output epilogue ----------------
#define BM 64
#define BN 64
#define BK 16
__global__ __launch_bounds__(256) void fused_out_kernel(const float* __restrict__ s,
                                                        const float* __restrict__ Wo,
                                                        const float* __restrict__ bo,
                                                        const float* __restrict__ W_po,
                                                        const float* __restrict__ b_po,
                                                        const float* __restrict__ w_scalar,
                                                        const float* __restrict__ w_point,
                                                        float* __restrict__ out) {
    int m0 = blockIdx.y * BM;
    int n0 = blockIdx.x * BN;
    __shared__ float As[BK][BM + 1];
    __shared__ float Bs[BK][BN + 1];
    int tid = threadIdx.x;
    int tx = tid % 16, ty = tid / 16;
    float acc1[4][4] = {};
    for (int kt = 0; kt < CH; kt += BK) {
#pragma unroll
        for (int p = 0; p < 4; p++) {
            int idx = p * 256 + tid;
            int ml = idx / BK, kl = idx % BK;
            As[kl][ml] = g_ao[(long)(m0 + ml) * CH + kt + kl];
        }
#pragma unroll
        for (int p = 0; p < 4; p++) {
            int idx = p * 256 + tid;
            int nl = idx / BK, kl = idx % BK;
            Bs[kl][nl] = Wo[(long)(n0 + nl) * CH + kt + kl];
        }
        __syncthreads();
#pragma unroll
        for (int k = 0; k < BK; k++) {
            float a[4], b[4];
#pragma unroll
            for (int i = 0; i < 4; i++) a[i] = As[k][ty * 4 + i];
#pragma unroll
            for (int j = 0; j < 4; j++) b[j] = Bs[k][tx * 4 + j];
#pragma unroll
            for (int i = 0; i < 4; i++)
#pragma unroll
                for (int j = 0; j < 4; j++) acc1[i][j] = fmaf(a[i], b[j], acc1[i][j]);
        }
        __syncthreads();
    }
    __shared__ float As2[BM][25];
    __shared__ float Bs2[BN][25];
    for (int idx = tid; idx < BM * 24; idx += 256)
        As2[idx / 24][idx % 24] = g_attpts[(long)(m0 + idx / 24) * 24 + idx % 24];
    for (int idx = tid; idx < BN * 24; idx += 256)
        Bs2[idx / 24][idx % 24] = W_po[(long)(n0 + idx / 24) * 24 + idx % 24];
    __syncthreads();
    float acc2[4][4] = {};
#pragma unroll
    for (int k = 0; k < 24; k++) {
        float a[4], b[4];
#pragma unroll
        for (int i = 0; i < 4; i++) a[i] = As2[ty * 4 + i][k];
#pragma unroll
        for (int j = 0; j < 4; j++) b[j] = Bs2[tx * 4 + j][k];
#pragma unroll
        for (int i = 0; i < 4; i++)
#pragma unroll
            for (int j = 0; j < 4; j++) acc2[i][j] = fmaf(a[i], b[j], acc2[i][j]);
    }
    float ws = *w_scalar, wp = *w_point;
#pragma unroll
    for (int i = 0; i < 4; i++) {
        int m = m0 + ty * 4 + i;
#pragma unroll
        for (int j = 0; j < 4; j++) {
            int n = n0 + tx * 4 + j;
            out[(long)m * CS + n] = s[(long)m * CS + n]
                + ws * (acc1[i][j] + bo[n])
                + wp * (acc2[i][j] + b_po[n]);
        }
    }
}

// ---------------- launch ----------------
extern "C" void kernel_launch(void* const* d_in, const int* in_sizes, int n_in,
                              void* d_out, int out_size) {
    const float* s       = (const float*)d_in[0];
    const float* z       = (const float*)d_in[1];
    const float* rigids  = (const float*)d_in[2];
    const float* mask    = (const float*)d_in[3];
    const float* ln_s_g  = (const float*)d_in[4];
    const float* ln_s_b  = (const float*)d_in[5];
    const float* ln_z_g  = (const float*)d_in[6];
    const float* ln_z_b  = (const float*)d_in[7];
    const float* Wq      = (const float*)d_in[8];
    const float* Wk      = (const float*)d_in[9];
    const float* Wv      = (const float*)d_in[10];
    const float* W_pair  = (const float*)d_in[11];
    const float* Wo      = (const float*)d_in[12];
    const float* bo      = (const float*)d_in[13];
    const float* Wvp     = (const float*)d_in[14];
    const float* bvp     = (const float*)d_in[15];
    const float* W_po    = (const float*)d_in[16];
    const float* b_po    = (const float*)d_in[17];
    const float* w_scalar= (const float*)d_in[18];
    const float* w_point = (const float*)d_in[19];
    float* out = (float*)d_out;

    static cudaStream_t s2;
    static cudaEvent_t ev_fork, ev_join;
    static int inited = 0;
    if (!inited) {
        cudaFuncSetAttribute(bias_softmax_kernel,
                             cudaFuncAttributeMaxDynamicSharedMemorySize, ZDYN_BYTES);
        cudaStreamCreateWithFlags(&s2, cudaStreamNonBlocking);
        cudaEventCreateWithFlags(&ev_fork, cudaEventDisableTiming);
        cudaEventCreateWithFlags(&ev_join, cudaEventDisableTiming);
        inited = 1;
    }

    // 1: fused prep
    prep_fused<<<S_LEN + 129 + 8 + 8, 128>>>(s, ln_s_g, ln_s_b, ln_z_g, ln_z_b, W_pair,
                                             Wq, Wk, Wv, Wvp, bvp, rigids, mask);

    // 2: qkvp (tensor core) -> fp32 + bf16 + vT
    {
        dim3 grid(QKVP_N / 64, S_LEN / 64, 1);
        qkvp_mma_kernel<<<grid, 256>>>();
    }

    // fork: point branch runs concurrently with qk + z-pass
    cudaEventRecord(ev_fork, 0);
    cudaStreamWaitEvent(s2, ev_fork, 0);
    vp_kernel<<<4, 256, 0, s2>>>();
    point_kernel<<<S_LEN, 256, 0, s2>>>(mask);
    cudaEventRecord(ev_join, s2);

    // 3: qk scores (tensor core, bf16 out, mask folded)
    {
        dim3 grid(S_LEN / 64, S_LEN / 64, NH);
        qk_mma_kernel<<<grid, 256>>>();
    }

    // 4: the big fused z pass
    bias_softmax_kernel<<<S_LEN, 256, ZDYN_BYTES>>>(z);

    // attn @ v (tensor core, split-K), then combine
    {
        dim3 grid(4, S_LEN / 64, NH);
        attnv_mma_kernel<<<grid, 256>>>();
        combine_ao_kernel<<<(S_LEN * CH + 255) / 256, 256>>>();
    }

    // join + fused output epilogue
    cudaStreamWaitEvent(0, ev_join, 0);
    {
        dim3 grid(CS / BN, S_LEN / BM, 1);
        fused_out_kernel<<<grid, 256>>>(s, Wo, bo, W_po, b_po, w_scalar, w_point, out);
    }
}

// round 17
// speedup vs baseline: 1.4978x; 1.0611x over previous
#include <cuda_runtime.h>
#include <cuda_bf16.h>
#include <math.h>

#define S_LEN 1024
#define CS 384
#define CZ 128
#define CH 256
#define NH 8
#define HD 32
#define PV 8
#define QKVP_N 832   // 256+256+256+64
#define INFV 100000.0f

#define ZTILE_ROWS 32
#define ZTILE_FLOATS (ZTILE_ROWS * CZ)   // 4096 floats = 16KB
#define NSTAGES 4
#define NTILES (S_LEN / ZTILE_ROWS)      // 32
#define ZDYN_BYTES (NSTAGES * ZTILE_FLOATS * 4)  // 65536

// ---------------- scratch (__device__ globals, no allocation) ----------------
__device__ __align__(16) __nv_bfloat16 g_sn_bf[S_LEN * CS];
__device__ __align__(16) __nv_bfloat16 g_Wall_bf[QKVP_N * CS];
__device__ __align__(16) float g_qkvp[S_LEN * QKVP_N];
__device__ __align__(16) __nv_bfloat16 g_qkvp_bf[S_LEN * QKVP_N];
__device__ __align__(16) __nv_bfloat16 g_vT_bf[CH * S_LEN];             // [d][j]
__device__ __align__(16) __nv_bfloat16 g_scores_bf[S_LEN * NH * S_LEN]; // [i][h][j]
__device__ __align__(16) __nv_bfloat16 g_biasbuf[S_LEN * S_LEN * NH];   // [i][j][h]
__device__ __align__(16) __nv_bfloat16 g_attn_bf[S_LEN * NH * S_LEN];   // [i][h][j]
__device__ __align__(16) float g_aop[4 * S_LEN * CH];
__device__ __align__(16) float g_ao[S_LEN * CH];
__device__ __align__(16) float g_bias832[QKVP_N];
__device__ __align__(16) float g_gw[NH * CZ];
__device__ float g_gwsum[NH];
__device__ float g_bw[NH];
__device__ __align__(16) float g_maskbias[S_LEN];
__device__ __align__(16) float g_coords[S_LEN * 4];
__device__ __align__(16) float g_vp[S_LEN * 24];
__device__ __align__(16) float g_attpts[S_LEN * 24];

// ---------------- packed f32x2 helpers ----------------
__device__ __forceinline__ unsigned long long pk(float x, float y) {
    float2 v = make_float2(x, y);
    return *reinterpret_cast<unsigned long long*>(&v);
}
__device__ __forceinline__ float2 upk(unsigned long long u) {
    return *reinterpret_cast<float2*>(&u);
}
__device__ __forceinline__ unsigned long long fma2(unsigned long long a,
                                                   unsigned long long b,
                                                   unsigned long long c) {
    unsigned long long d;
    asm("fma.rn.f32x2 %0, %1, %2, %3;" : "=l"(d) : "l"(a), "l"(b), "l"(c));
    return d;
}
__device__ __forceinline__ unsigned long long add2(unsigned long long a,
                                                   unsigned long long b) {
    unsigned long long d;
    asm("add.rn.f32x2 %0, %1, %2;" : "=l"(d) : "l"(a), "l"(b));
    return d;
}

#define MMA16816(c0, c1, c2, c3, a0, a1, a2, a3, b0, b1)                     \
    asm volatile(                                                            \
        "mma.sync.aligned.m16n8k16.row.col.f32.bf16.bf16.f32 "               \
        "{%0,%1,%2,%3}, {%4,%5,%6,%7}, {%8,%9}, {%0,%1,%2,%3};"              \
        : "+f"(c0), "+f"(c1), "+f"(c2), "+f"(c3)                             \
        : "r"(a0), "r"(a1), "r"(a2), "r"(a3), "r"(b0), "r"(b1))

// ---------------- fused prep ----------------
__global__ void prep_fused(const float* __restrict__ s,
                           const float* __restrict__ ln_s_g, const float* __restrict__ ln_s_b,
                           const float* __restrict__ ln_z_g, const float* __restrict__ ln_z_b,
                           const float* __restrict__ W_pair,
                           const float* __restrict__ Wq, const float* __restrict__ Wk,
                           const float* __restrict__ Wv, const float* __restrict__ Wvp,
                           const float* __restrict__ bvp, const float* __restrict__ rigids,
                           const float* __restrict__ mask) {
    int b = blockIdx.x;
    int t = threadIdx.x;  // 128
    __shared__ float red[128];
    if (b < S_LEN) {
        const float* row = s + (long)b * CS;
        float x0 = row[t], x1 = row[t + 128], x2 = row[t + 256];
        red[t] = x0 + x1 + x2; __syncthreads();
        for (int st = 64; st > 0; st >>= 1) { if (t < st) red[t] += red[t + st]; __syncthreads(); }
        float mean = red[0] * (1.0f / CS);
        __syncthreads();
        float d0 = x0 - mean, d1 = x1 - mean, d2 = x2 - mean;
        red[t] = d0 * d0 + d1 * d1 + d2 * d2; __syncthreads();
        for (int st = 64; st > 0; st >>= 1) { if (t < st) red[t] += red[t + st]; __syncthreads(); }
        float r = rsqrtf(red[0] * (1.0f / CS) + 1e-5f);
        __nv_bfloat16* o = g_sn_bf + (long)b * CS;
        o[t]       = __float2bfloat16(d0 * r * ln_s_g[t]       + ln_s_b[t]);
        o[t + 128] = __float2bfloat16(d1 * r * ln_s_g[t + 128] + ln_s_b[t + 128]);
        o[t + 256] = __float2bfloat16(d2 * r * ln_s_g[t + 256] + ln_s_b[t + 256]);
    } else if (b < S_LEN + 128) {
        int t2 = (b - S_LEN) * 128 + t;
        for (int idx = t2; idx < QKVP_N * CS; idx += 128 * 128) {
            int r = idx / CS, c = idx % CS;
            float v;
            if (r < 256)      v = Wq[r * CS + c];
            else if (r < 512) v = Wk[(r - 256) * CS + c];
            else if (r < 768) v = Wv[(r - 512) * CS + c];
            else              v = Wvp[(r - 768) * CS + c];
            g_Wall_bf[idx] = __float2bfloat16(v);
        }
        if (t2 < QKVP_N) g_bias832[t2] = (t2 >= 768) ? bvp[t2 - 768] : 0.0f;
    } else if (b == S_LEN + 128) {
        int c = t;  // 128
        for (int h = 0; h < NH; h++) {
            float w = W_pair[h * CZ + c];
            float gv = ln_z_g[c] * w;
            g_gw[h * CZ + c] = gv;
            red[c] = gv; __syncthreads();
            for (int st = 64; st > 0; st >>= 1) { if (c < st) red[c] += red[c + st]; __syncthreads(); }
            if (c == 0) g_gwsum[h] = red[0];
            __syncthreads();
            red[c] = ln_z_b[c] * w; __syncthreads();
            for (int st = 64; st > 0; st >>= 1) { if (c < st) red[c] += red[c + st]; __syncthreads(); }
            if (c == 0) g_bw[h] = red[0];
            __syncthreads();
        }
    } else if (b < S_LEN + 129 + 8) {
        int i = (b - (S_LEN + 129)) * 128 + t;
        if (i < S_LEN) {
            const float* rg = rigids + i * 16;
            float4 c;
            c.x = rg[3]; c.y = rg[7]; c.z = rg[11]; c.w = 0.0f;
            ((float4*)g_coords)[i] = c;
        }
    } else {
        int i = (b - (S_LEN + 137)) * 128 + t;
        if (i < S_LEN) {
            const float inv_scale = 5.656854249492381f;  // sqrt(32)
            g_maskbias[i] = INFV * (mask[i] - 1.0f) * inv_scale;
        }
    }
}

// ---------------- qkvp via bf16 mma; emits fp32 + bf16 + vT ----------------
#define AS_STRIDE 24
__global__ __launch_bounds__(256) void qkvp_mma_kernel() {
    __shared__ __nv_bfloat16 As[64][AS_STRIDE];
    __shared__ __nv_bfloat16 Bs[64][AS_STRIDE];
    int tid = threadIdx.x;
    int warp = tid >> 5, lane = tid & 31;
    int m0 = blockIdx.y * 64, n0 = blockIdx.x * 64;
    int wm = (warp & 3) * 16, wn = (warp >> 2) * 32;
    int g = lane >> 2, t = lane & 3;

    float c[4][4] = {};
    for (int kt = 0; kt < CS; kt += 16) {
#pragma unroll
        for (int p = 0; p < 2; p++) {
            int idx = tid + p * 256;
            int row = idx >> 3, cc = (idx & 7) * 2;
            *(unsigned*)&As[row][cc] =
                *(const unsigned*)&g_sn_bf[(long)(m0 + row) * CS + kt + cc];
            *(unsigned*)&Bs[row][cc] =
                *(const unsigned*)&g_Wall_bf[(long)(n0 + row) * CS + kt + cc];
        }
        __syncthreads();
        unsigned a0 = *(const unsigned*)&As[wm + g][t * 2];
        unsigned a1 = *(const unsigned*)&As[wm + g + 8][t * 2];
        unsigned a2 = *(const unsigned*)&As[wm + g][t * 2 + 8];
        unsigned a3 = *(const unsigned*)&As[wm + g + 8][t * 2 + 8];
#pragma unroll
        for (int f = 0; f < 4; f++) {
            unsigned b0 = *(const unsigned*)&Bs[wn + f * 8 + g][t * 2];
            unsigned b1 = *(const unsigned*)&Bs[wn + f * 8 + g][t * 2 + 8];
            MMA16816(c[f][0], c[f][1], c[f][2], c[f][3], a0, a1, a2, a3, b0, b1);
        }
        __syncthreads();
    }
#pragma unroll
    for (int f = 0; f < 4; f++) {
        int col = n0 + wn + f * 8 + t * 2;
        float b0 = g_bias832[col], b1 = g_bias832[col + 1];
        int row0 = m0 + wm + g, row1 = row0 + 8;
        float v00 = c[f][0] + b0, v01 = c[f][1] + b1;
        float v10 = c[f][2] + b0, v11 = c[f][3] + b1;
        *(float2*)&g_qkvp[(long)row0 * QKVP_N + col] = make_float2(v00, v01);
        *(float2*)&g_qkvp[(long)row1 * QKVP_N + col] = make_float2(v10, v11);
        *(__nv_bfloat162*)&g_qkvp_bf[(long)row0 * QKVP_N + col] = __floats2bfloat162_rn(v00, v01);
        *(__nv_bfloat162*)&g_qkvp_bf[(long)row1 * QKVP_N + col] = __floats2bfloat162_rn(v10, v11);
        if (col >= 512 && col < 768) {
            int d = col - 512;
            g_vT_bf[(long)d * S_LEN + row0]       = __float2bfloat16(v00);
            g_vT_bf[(long)(d + 1) * S_LEN + row0] = __float2bfloat16(v01);
            g_vT_bf[(long)d * S_LEN + row1]       = __float2bfloat16(v10);
            g_vT_bf[(long)(d + 1) * S_LEN + row1] = __float2bfloat16(v11);
        }
    }
}

// ---------------- qk scores via bf16 mma: bf16 output ----------------
__global__ __launch_bounds__(256) void qk_mma_kernel() {
    __shared__ __nv_bfloat16 As[64][40];
    __shared__ __nv_bfloat16 Bs[64][40];
    int tid = threadIdx.x;
    int warp = tid >> 5, lane = tid & 31;
    int h = blockIdx.z;
    int m0 = blockIdx.y * 64, n0 = blockIdx.x * 64;
    int wm = (warp & 3) * 16, wn = (warp >> 2) * 32;
    int g = lane >> 2, t = lane & 3;

    const __nv_bfloat16* qb = g_qkvp_bf + h * 32;
    const __nv_bfloat16* kb = g_qkvp_bf + 256 + h * 32;
#pragma unroll
    for (int p = 0; p < 4; p++) {
        int idx = tid + p * 256;
        int row = idx >> 4, cc = (idx & 15) * 2;
        *(unsigned*)&As[row][cc] = *(const unsigned*)&qb[(long)(m0 + row) * QKVP_N + cc];
        *(unsigned*)&Bs[row][cc] = *(const unsigned*)&kb[(long)(n0 + row) * QKVP_N + cc];
    }
    __syncthreads();
    float c[4][4] = {};
#pragma unroll
    for (int ks = 0; ks < 2; ks++) {
        unsigned a0 = *(const unsigned*)&As[wm + g][ks * 16 + t * 2];
        unsigned a1 = *(const unsigned*)&As[wm + g + 8][ks * 16 + t * 2];
        unsigned a2 = *(const unsigned*)&As[wm + g][ks * 16 + t * 2 + 8];
        unsigned a3 = *(const unsigned*)&As[wm + g + 8][ks * 16 + t * 2 + 8];
#pragma unroll
        for (int f = 0; f < 4; f++) {
            unsigned b0 = *(const unsigned*)&Bs[wn + f * 8 + g][ks * 16 + t * 2];
            unsigned b1 = *(const unsigned*)&Bs[wn + f * 8 + g][ks * 16 + t * 2 + 8];
            MMA16816(c[f][0], c[f][1], c[f][2], c[f][3], a0, a1, a2, a3, b0, b1);
        }
    }
    const float scale = 0.17677669529663687f;
#pragma unroll
    for (int f = 0; f < 4; f++) {
        int col = n0 + wn + f * 8 + t * 2;
        float mb0 = g_maskbias[col], mb1 = g_maskbias[col + 1];
        int row0 = m0 + wm + g, row1 = row0 + 8;
        *(__nv_bfloat162*)&g_scores_bf[((long)row0 * NH + h) * S_LEN + col] =
            __floats2bfloat162_rn((c[f][0] + mb0) * scale, (c[f][1] + mb1) * scale);
        *(__nv_bfloat162*)&g_scores_bf[((long)row1 * NH + h) * S_LEN + col] =
            __floats2bfloat162_rn((c[f][2] + mb0) * scale, (c[f][3] + mb1) * scale);
    }
}

// ---------------- bias kernel (z-pass main loop only; bias -> gmem bf16 [i][j][h]) ----------------
__global__ __launch_bounds__(256) void bias_kernel(const float* __restrict__ z) {
    extern __shared__ __align__(16) float zbuf[];  // 64KB

    int i = blockIdx.x;
    int tid = threadIdx.x;  // 256
    int w = tid >> 5, lane = tid & 31;
    int sub = lane >> 4, r16 = lane & 15;

    unsigned long long wa01[NH], wa23[NH], wc01[NH], wc23[NH];
#pragma unroll
    for (int h = 0; h < NH; h++) {
        float4 wa = *(const float4*)(g_gw + h * CZ + r16 * 4);
        float4 wc = *(const float4*)(g_gw + h * CZ + 64 + r16 * 4);
        wa01[h] = pk(wa.x, wa.y); wa23[h] = pk(wa.z, wa.w);
        wc01[h] = pk(wc.x, wc.y); wc23[h] = pk(wc.z, wc.w);
    }
    int h_own = (r16 >> 1) & 7;
    float gws_own = g_gwsum[h_own];
    float bw_own  = g_bw[h_own];
    bool wr_lane = ((r16 & 1) == 0);
    bool b3 = (r16 & 8) != 0, b2 = (r16 & 4) != 0, b1 = (r16 & 2) != 0;

    const float* zbase = z + ((long)i << 17);
    __nv_bfloat16* brow = g_biasbuf + ((long)i << 13);  // [j][h]

#define ISSUE_TILE(T)                                                                   \
    do {                                                                                \
        if ((T) < NTILES) {                                                             \
            const float4* src = (const float4*)(zbase + (long)(T) * ZTILE_FLOATS);      \
            float4* dst = (float4*)(zbuf + ((T) % NSTAGES) * ZTILE_FLOATS);             \
            _Pragma("unroll")                                                           \
            for (int p = 0; p < 4; p++) {                                               \
                int c = tid + p * 256;                                                  \
                unsigned saddr = (unsigned)__cvta_generic_to_shared(dst + c);           \
                asm volatile("cp.async.cg.shared.global [%0], [%1], 16;"                \
                             :: "r"(saddr), "l"(src + c));                              \
            }                                                                           \
        }                                                                               \
        asm volatile("cp.async.commit_group;" ::);                                      \
    } while (0)

    ISSUE_TILE(0); ISSUE_TILE(1); ISSUE_TILE(2);

    for (int t = 0; t < NTILES; t++) {
        asm volatile("cp.async.wait_group %0;" :: "n"(2));
        __syncthreads();
        const float* sb = zbuf + (t % NSTAGES) * ZTILE_FLOATS;
#pragma unroll
        for (int it = 0; it < 2; it++) {
            int lrow = it * 16 + 2 * w + sub;
            const float4* zr = (const float4*)(sb + lrow * CZ);
            float4 A0 = zr[r16];
            float4 A1 = zr[16 + r16];
            unsigned long long za01 = pk(A0.x, A0.y), za23 = pk(A0.z, A0.w);
            unsigned long long zc01 = pk(A1.x, A1.y), zc23 = pk(A1.z, A1.w);
            unsigned long long sz2  = add2(add2(za01, za23), add2(zc01, zc23));
            unsigned long long szz2 = fma2(za01, za01, fma2(za23, za23,
                                      fma2(zc01, zc01, fma2(zc23, zc23, 0ull))));
            float dot[NH];
#pragma unroll
            for (int h = 0; h < NH; h++) {
                unsigned long long d2 = fma2(za01, wa01[h], fma2(za23, wa23[h],
                                        fma2(zc01, wc01[h], fma2(zc23, wc23[h], 0ull))));
                float2 d = upk(d2);
                dot[h] = d.x + d.y;
            }
            float2 s2 = upk(sz2);  float sz  = s2.x + s2.y;
            float2 q2 = upk(szz2); float szz = q2.x + q2.y;

#pragma unroll
            for (int o = 8; o >= 1; o >>= 1) {
                sz  += __shfl_xor_sync(0xffffffffu, sz, o);
                szz += __shfl_xor_sync(0xffffffffu, szz, o);
            }
#pragma unroll
            for (int k = 0; k < 8; k++) dot[k] += __shfl_xor_sync(0xffffffffu, dot[k], 8);
            float y0 = b3 ? dot[4] : dot[0];
            float y1 = b3 ? dot[5] : dot[1];
            float y2 = b3 ? dot[6] : dot[2];
            float y3 = b3 ? dot[7] : dot[3];
            y0 += __shfl_xor_sync(0xffffffffu, y0, 4);
            y1 += __shfl_xor_sync(0xffffffffu, y1, 4);
            y2 += __shfl_xor_sync(0xffffffffu, y2, 4);
            y3 += __shfl_xor_sync(0xffffffffu, y3, 4);
            float t0 = b2 ? y2 : y0;
            float t1 = b2 ? y3 : y1;
            t0 += __shfl_xor_sync(0xffffffffu, t0, 2);
            t1 += __shfl_xor_sync(0xffffffffu, t1, 2);
            float f = b1 ? t1 : t0;
            f += __shfl_xor_sync(0xffffffffu, f, 1);

            float mean = sz * (1.0f / CZ);
            float var = szz * (1.0f / CZ) - mean * mean;
            float r = rsqrtf(var + 1e-5f);
            if (wr_lane) {
                int j = t * ZTILE_ROWS + lrow;
                brow[j * NH + h_own] =
                    __float2bfloat16(r * f - r * mean * gws_own + bw_own);
            }
        }
        __syncthreads();
        ISSUE_TILE(t + 3);
    }
#undef ISSUE_TILE
}

// ---------------- softmax kernel: smem-transposed bias + bf16 scores -> bf16 attn ----------------
#define BPITCH 10
__global__ __launch_bounds__(256) void softmax_kernel() {
    __shared__ __nv_bfloat16 sb[S_LEN * BPITCH];   // 20KB
    int i = blockIdx.x;
    int tid = threadIdx.x;
    int w = tid >> 5, lane = tid & 31;

    // stage bias[i][j][h] (coalesced u32 reads) into pitch-10 rows
    const unsigned* src = (const unsigned*)(g_biasbuf + ((long)i << 13));
    for (int idx = tid; idx < 4096; idx += 256) {
        unsigned v = src[idx];
        int j = idx >> 2;
        int c = (idx & 3) * 2;
        *(unsigned*)&sb[j * BPITCH + c] = v;   // (j*10+c) even -> 4B aligned
    }
    __syncthreads();

    const __nv_bfloat16* qk = g_scores_bf + ((long)i * NH + w) * S_LEN;
    float v[32];
    float m = -1e30f;
#pragma unroll
    for (int q = 0; q < 32; q++) {
        int jj = q * 32 + lane;
        float val = __bfloat162float(qk[jj]) + __bfloat162float(sb[jj * BPITCH + w]);
        v[q] = val;
        m = fmaxf(m, val);
    }
#pragma unroll
    for (int o = 16; o > 0; o >>= 1) m = fmaxf(m, __shfl_xor_sync(0xffffffffu, m, o));
    float ssum = 0.0f;
#pragma unroll
    for (int q = 0; q < 32; q++) {
        float e = __expf(v[q] - m);
        v[q] = e;
        ssum += e;
    }
#pragma unroll
    for (int o = 16; o > 0; o >>= 1) ssum += __shfl_xor_sync(0xffffffffu, ssum, o);
    float rinv = 1.0f / ssum;
    __nv_bfloat16* outp = g_attn_bf + ((long)i * NH + w) * S_LEN;
#pragma unroll
    for (int q = 0; q < 32; q++)
        outp[q * 32 + lane] = __float2bfloat16(v[q] * rinv);
}

// ---------------- attn @ v via bf16 mma: split-K=4 ----------------
__global__ __launch_bounds__(256) void attnv_mma_kernel() {
    __shared__ __nv_bfloat16 As[64][72];
    __shared__ __nv_bfloat16 Bs[32][72];
    int tid = threadIdx.x;
    int warp = tid >> 5, lane = tid & 31;
    int ks = blockIdx.x;
    int m0 = blockIdx.y * 64;
    int h = blockIdx.z;
    int wm = (warp & 3) * 16, wn = (warp >> 2) * 16;
    int g = lane >> 2, t = lane & 3;
    const __nv_bfloat16* A = g_attn_bf + (long)h * S_LEN;

    float c[2][4] = {};
    int k0 = ks * 256;
    for (int kt = 0; kt < 4; kt++) {
#pragma unroll
        for (int p = 0; p < 8; p++) {
            int idx = tid + p * 256;
            int row = idx >> 5, cc = (idx & 31) * 2;
            *(unsigned*)&As[row][cc] =
                *(const unsigned*)&A[(long)(m0 + row) * (NH * S_LEN) + k0 + kt * 64 + cc];
        }
#pragma unroll
        for (int p = 0; p < 4; p++) {
            int idx = tid + p * 256;
            int row = idx >> 5, cc = (idx & 31) * 2;
            *(unsigned*)&Bs[row][cc] =
                *(const unsigned*)&g_vT_bf[(long)(h * 32 + row) * S_LEN + k0 + kt * 64 + cc];
        }
        __syncthreads();
#pragma unroll
        for (int ko = 0; ko < 4; ko++) {
            unsigned a0 = *(const unsigned*)&As[wm + g][ko * 16 + t * 2];
            unsigned a1 = *(const unsigned*)&As[wm + g + 8][ko * 16 + t * 2];
            unsigned a2 = *(const unsigned*)&As[wm + g][ko * 16 + t * 2 + 8];
            unsigned a3 = *(const unsigned*)&As[wm + g + 8][ko * 16 + t * 2 + 8];
#pragma unroll
            for (int f = 0; f < 2; f++) {
                unsigned b0 = *(const unsigned*)&Bs[wn + f * 8 + g][ko * 16 + t * 2];
                unsigned b1 = *(const unsigned*)&Bs[wn + f * 8 + g][ko * 16 + t * 2 + 8];
                MMA16816(c[f][0], c[f][1], c[f][2], c[f][3], a0, a1, a2, a3, b0, b1);
            }
        }
        __syncthreads();
    }
    float* C = g_aop + (long)ks * (S_LEN * CH);
#pragma unroll
    for (int f = 0; f < 2; f++) {
        int col = h * 32 + wn + f * 8 + t * 2;
        int row0 = m0 + wm + g, row1 = row0 + 8;
        *(float2*)&C[(long)row0 * CH + col] = make_float2(c[f][0], c[f][1]);
        *(float2*)&C[(long)row1 * CH + col] = make_float2(c[f][2], c[f][3]);
    }
}

__global__ void combine_ao_kernel() {
    int idx = blockIdx.x * blockDim.x + threadIdx.x;
    if (idx < S_LEN * CH)
        g_ao[idx] = g_aop[idx] + g_aop[S_LEN * CH + idx] +
                    g_aop[2 * S_LEN * CH + idx] + g_aop[3 * S_LEN * CH + idx];
}

// ---------------- point branch ----------------
__global__ void vp_kernel() {
    int i = blockIdx.x * blockDim.x + threadIdx.x;
    if (i >= S_LEN) return;
    float4 c = ((const float4*)g_coords)[i];
    const float* row = g_qkvp + (long)i * QKVP_N + 768;
#pragma unroll
    for (int h = 0; h < NH; h++) {
        float sm = 0.0f;
#pragma unroll
        for (int p = 0; p < PV; p++) sm += row[h * PV + p];
        g_vp[i * 24 + h * 3 + 0] = sm * c.x;
        g_vp[i * 24 + h * 3 + 1] = sm * c.y;
        g_vp[i * 24 + h * 3 + 2] = sm * c.z;
    }
}

__global__ __launch_bounds__(256) void point_kernel(const float* __restrict__ mask) {
    int i = blockIdx.x;
    int tid = threadIdx.x;  // 256
    __shared__ float svp[256 * 25];
    __shared__ float4 sco[256];
    __shared__ float sred[8 * 25];

    float4 ci = ((const float4*)g_coords)[i];
    float mi = mask[i];
    float acc[24] = {};
    float sw = 0.0f;

    for (int jt = 0; jt < 4; jt++) {
        int jbase = jt * 256;
        for (int idx = tid; idx < 256 * 24; idx += 256)
            svp[(idx / 24) * 25 + (idx % 24)] = g_vp[jbase * 24 + idx];
        sco[tid] = ((const float4*)g_coords)[jbase + tid];
        __syncthreads();
        int jl = tid;
        float4 cj = sco[jl];
        float dx = ci.x - cj.x, dy = ci.y - cj.y, dz = ci.z - cj.z;
        float dist = sqrtf(dx * dx + dy * dy + dz * dz + 1e-12f);
        float wgt = __expf(-dist * 0.1f) * mi * mask[jbase + jl];
        sw += wgt;
#pragma unroll
        for (int p = 0; p < 24; p++) acc[p] = fmaf(wgt, svp[jl * 25 + p], acc[p]);
        __syncthreads();
    }

    int wr = tid >> 5, lane = tid & 31;
#pragma unroll
    for (int o = 16; o > 0; o >>= 1) {
        sw += __shfl_xor_sync(0xffffffffu, sw, o);
#pragma unroll
        for (int p = 0; p < 24; p++) acc[p] += __shfl_xor_sync(0xffffffffu, acc[p], o);
    }
    if (lane == 0) {
#pragma unroll
        for (int p = 0; p < 24; p++) sred[wr * 25 + p] = acc[p];
        sred[wr * 25 + 24] = sw;
    }
    __syncthreads();
    if (tid < 24) {
        float s = 0.0f, swt = 0.0f;
#pragma unroll
        for (int k = 0; k < 8; k++) { s += sred[k * 25 + tid]; swt += sred[k * 25 + 24]; }
        g_attpts[i * 24 + tid] = s / (swt + 1e-8f);
    }
}

// ---------------- fused output epilogue ----------------
#define BM 64
#define BN 64
#define BK 16
__global__ __launch_bounds__(256) void fused_out_kernel(const float* __restrict__ s,
                                                        const float* __restrict__ Wo,
                                                        const float* __restrict__ bo,
                                                        const float* __restrict__ W_po,
                                                        const float* __restrict__ b_po,
                                                        const float* __restrict__ w_scalar,
                                                        const float* __restrict__ w_point,
                                                        float* __restrict__ out) {
    int m0 = blockIdx.y * BM;
    int n0 = blockIdx.x * BN;
    __shared__ float As[BK][BM + 1];
    __shared__ float Bs[BK][BN + 1];
    int tid = threadIdx.x;
    int tx = tid % 16, ty = tid / 16;
    float acc1[4][4] = {};
    for (int kt = 0; kt < CH; kt += BK) {
#pragma unroll
        for (int p = 0; p < 4; p++) {
            int idx = p * 256 + tid;
            int ml = idx / BK, kl = idx % BK;
            As[kl][ml] = g_ao[(long)(m0 + ml) * CH + kt + kl];
        }
#pragma unroll
        for (int p = 0; p < 4; p++) {
            int idx = p * 256 + tid;
            int nl = idx / BK, kl = idx % BK;
            Bs[kl][nl] = Wo[(long)(n0 + nl) * CH + kt + kl];
        }
        __syncthreads();
#pragma unroll
        for (int k = 0; k < BK; k++) {
            float a[4], b[4];
#pragma unroll
            for (int i = 0; i < 4; i++) a[i] = As[k][ty * 4 + i];
#pragma unroll
            for (int j = 0; j < 4; j++) b[j] = Bs[k][tx * 4 + j];
#pragma unroll
            for (int i = 0; i < 4; i++)
#pragma unroll
                for (int j = 0; j < 4; j++) acc1[i][j] = fmaf(a[i], b[j], acc1[i][j]);
        }
        __syncthreads();
    }
    __shared__ float As2[BM][25];
    __shared__ float Bs2[BN][25];
    for (int idx = tid; idx < BM * 24; idx += 256)
        As2[idx / 24][idx % 24] = g_attpts[(long)(m0 + idx / 24) * 24 + idx % 24];
    for (int idx = tid; idx < BN * 24; idx += 256)
        Bs2[idx / 24][idx % 24] = W_po[(long)(n0 + idx / 24) * 24 + idx % 24];
    __syncthreads();
    float acc2[4][4] = {};
#pragma unroll
    for (int k = 0; k < 24; k++) {
        float a[4], b[4];
#pragma unroll
        for (int i = 0; i < 4; i++) a[i] = As2[ty * 4 + i][k];
#pragma unroll
        for (int j = 0; j < 4; j++) b[j] = Bs2[tx * 4 + j][k];
#pragma unroll
        for (int i = 0; i < 4; i++)
#pragma unroll
            for (int j = 0; j < 4; j++) acc2[i][j] = fmaf(a[i], b[j], acc2[i][j]);
    }
    float ws = *w_scalar, wp = *w_point;
#pragma unroll
    for (int i = 0; i < 4; i++) {
        int m = m0 + ty * 4 + i;
#pragma unroll
        for (int j = 0; j < 4; j++) {
            int n = n0 + tx * 4 + j;
            out[(long)m * CS + n] = s[(long)m * CS + n]
                + ws * (acc1[i][j] + bo[n])
                + wp * (acc2[i][j] + b_po[n]);
        }
    }
}

// ---------------- launch ----------------
extern "C" void kernel_launch(void* const* d_in, const int* in_sizes, int n_in,
                              void* d_out, int out_size) {
    const float* s       = (const float*)d_in[0];
    const float* z       = (const float*)d_in[1];
    const float* rigids  = (const float*)d_in[2];
    const float* mask    = (const float*)d_in[3];
    const float* ln_s_g  = (const float*)d_in[4];
    const float* ln_s_b  = (const float*)d_in[5];
    const float* ln_z_g  = (const float*)d_in[6];
    const float* ln_z_b  = (const float*)d_in[7];
    const float* Wq      = (const float*)d_in[8];
    const float* Wk      = (const float*)d_in[9];
    const float* Wv      = (const float*)d_in[10];
    const float* W_pair  = (const float*)d_in[11];
    const float* Wo      = (const float*)d_in[12];
    const float* bo      = (const float*)d_in[13];
    const float* Wvp     = (const float*)d_in[14];
    const float* bvp     = (const float*)d_in[15];
    const float* W_po    = (const float*)d_in[16];
    const float* b_po    = (const float*)d_in[17];
    const float* w_scalar= (const float*)d_in[18];
    const float* w_point = (const float*)d_in[19];
    float* out = (float*)d_out;

    static cudaStream_t s2, s3;
    static cudaEvent_t ev_prep, ev_qkvp, ev_bias, ev_point;
    static int inited = 0;
    if (!inited) {
        cudaFuncSetAttribute(bias_kernel,
                             cudaFuncAttributeMaxDynamicSharedMemorySize, ZDYN_BYTES);
        cudaStreamCreateWithFlags(&s2, cudaStreamNonBlocking);
        cudaStreamCreateWithFlags(&s3, cudaStreamNonBlocking);
        cudaEventCreateWithFlags(&ev_prep,  cudaEventDisableTiming);
        cudaEventCreateWithFlags(&ev_qkvp,  cudaEventDisableTiming);
        cudaEventCreateWithFlags(&ev_bias,  cudaEventDisableTiming);
        cudaEventCreateWithFlags(&ev_point, cudaEventDisableTiming);
        inited = 1;
    }

    // 1: fused prep (main)
    prep_fused<<<S_LEN + 129 + 8 + 8, 128>>>(s, ln_s_g, ln_s_b, ln_z_g, ln_z_b, W_pair,
                                             Wq, Wk, Wv, Wvp, bvp, rigids, mask);
    cudaEventRecord(ev_prep, 0);

    // s2: the big z bias pass, concurrent with qkvp + qk on main
    cudaStreamWaitEvent(s2, ev_prep, 0);
    bias_kernel<<<S_LEN, 256, ZDYN_BYTES, s2>>>(z);
    cudaEventRecord(ev_bias, s2);

    // 2: qkvp (tensor core) on main
    {
        dim3 grid(QKVP_N / 64, S_LEN / 64, 1);
        qkvp_mma_kernel<<<grid, 256>>>();
    }
    cudaEventRecord(ev_qkvp, 0);

    // s3: point branch, concurrent
    cudaStreamWaitEvent(s3, ev_qkvp, 0);
    vp_kernel<<<4, 256, 0, s3>>>();
    point_kernel<<<S_LEN, 256, 0, s3>>>(mask);
    cudaEventRecord(ev_point, s3);

    // 3: qk scores (tensor core) on main
    {
        dim3 grid(S_LEN / 64, S_LEN / 64, NH);
        qk_mma_kernel<<<grid, 256>>>();
    }

    // join bias, then softmax
    cudaStreamWaitEvent(0, ev_bias, 0);
    softmax_kernel<<<S_LEN, 256>>>();

    // attn @ v (tensor core, split-K), then combine
    {
        dim3 grid(4, S_LEN / 64, NH);
        attnv_mma_kernel<<<grid, 256>>>();
        combine_ao_kernel<<<(S_LEN * CH + 255) / 256, 256>>>();
    }

    // join point branch + fused output epilogue
    cudaStreamWaitEvent(0, ev_point, 0);
    {
        dim3 grid(CS / BN, S_LEN / BM, 1);
        fused_out_kernel<<<grid, 256>>>(s, Wo, bo, W_po, b_po, w_scalar, w_point, out);
    }
}